// round 2
// baseline (speedup 1.0000x reference)
#include <cuda_runtime.h>

#define Bn   4
#define Sn   4096
#define Dn   1024
#define Hn   16
#define HKVn 4
#define DHn  64
#define Mtok (Bn*Sn)            // 16384

// ---- scratch (static device globals: allowed) ----
__device__ float g_q  [Mtok * Hn   * DHn];   // [tok][h*dh]
__device__ float g_k  [Mtok * HKVn * DHn];
__device__ float g_v  [Mtok * HKVn * DHn];
__device__ float g_qt [Bn * Hn   * Sn * DHn]; // [b][h][s][dh]
__device__ float g_kt [Bn * HKVn * Sn * DHn];
__device__ float g_vt [Bn * HKVn * Sn * DHn];
__device__ float g_att[Mtok * Hn * DHn];      // [tok][h*dh]

// ============================================================
// SGEMM: C[M,N] = A[M,K] @ B[K,N] + bias[N]
// 128x128 tile, BK=8, 256 threads, 8x8 register tile / thread.
// Requires M%128==0, N%128==0, K%8==0 (true for all calls here).
// ============================================================
__global__ __launch_bounds__(256) void sgemm_bias_kernel(
    const float* __restrict__ A, const float* __restrict__ Bw,
    const float* __restrict__ bias, float* __restrict__ Cm,
    int M, int N, int K)
{
    __shared__ float As[8][128];
    __shared__ float Bs[8][128];

    const int t  = threadIdx.x;
    const int m0 = blockIdx.y * 128;
    const int n0 = blockIdx.x * 128;
    const int ty = t >> 4;          // 0..15
    const int tx = t & 15;          // 0..15
    const int arow = t >> 1, acol = (t & 1) * 4;
    const int brow = t >> 5, bcol = (t & 31) * 4;

    const float* Ap = A + (size_t)(m0 + arow) * K + acol;
    const float* Bp = Bw + (size_t)brow * N + n0 + bcol;

    float acc[8][8] = {};

    for (int k0 = 0; k0 < K; k0 += 8) {
        float4 av = *(const float4*)(Ap + k0);
        float4 bv = *(const float4*)(Bp + (size_t)k0 * N);
        As[acol + 0][arow] = av.x;
        As[acol + 1][arow] = av.y;
        As[acol + 2][arow] = av.z;
        As[acol + 3][arow] = av.w;
        *(float4*)&Bs[brow][bcol] = bv;
        __syncthreads();
#pragma unroll
        for (int kk = 0; kk < 8; kk++) {
            float ar[8], br[8];
            *(float4*)(ar)     = *(const float4*)&As[kk][ty * 8];
            *(float4*)(ar + 4) = *(const float4*)&As[kk][ty * 8 + 4];
            *(float4*)(br)     = *(const float4*)&Bs[kk][tx * 8];
            *(float4*)(br + 4) = *(const float4*)&Bs[kk][tx * 8 + 4];
#pragma unroll
            for (int i = 0; i < 8; i++)
#pragma unroll
                for (int j = 0; j < 8; j++)
                    acc[i][j] += ar[i] * br[j];
        }
        __syncthreads();
    }

    float breg[8];
#pragma unroll
    for (int j = 0; j < 8; j++) breg[j] = bias[n0 + tx * 8 + j];

#pragma unroll
    for (int i = 0; i < 8; i++) {
        int row = m0 + ty * 8 + i;
        float* cp = Cm + (size_t)row * N + n0 + tx * 8;
        float4 o0, o1;
        o0.x = acc[i][0] + breg[0]; o0.y = acc[i][1] + breg[1];
        o0.z = acc[i][2] + breg[2]; o0.w = acc[i][3] + breg[3];
        o1.x = acc[i][4] + breg[4]; o1.y = acc[i][5] + breg[5];
        o1.z = acc[i][6] + breg[6]; o1.w = acc[i][7] + breg[7];
        *(float4*)cp       = o0;
        *(float4*)(cp + 4) = o1;
    }
}

// ============================================================
// RMSNorm + RoPE + transpose to [b][h][s][dh] layouts.
// One block per token; warp handles one (token, head) row of 64.
// ============================================================
__global__ __launch_bounds__(256) void norm_rope_kernel(
    const float* __restrict__ q, const float* __restrict__ k, const float* __restrict__ v,
    const float* __restrict__ qn, const float* __restrict__ kn,
    const float* __restrict__ cosT, const float* __restrict__ sinT,
    float* __restrict__ qt, float* __restrict__ kt, float* __restrict__ vt)
{
    const int tok  = blockIdx.x;
    const int b    = tok >> 12;       // / 4096
    const int s    = tok & 4095;
    const int warp = threadIdx.x >> 5;
    const int lane = threadIdx.x & 31;

    const float c0 = cosT[s * 64 + lane];
    const float c1 = cosT[s * 64 + lane + 32];
    const float s0 = sinT[s * 64 + lane];
    const float s1 = sinT[s * 64 + lane + 32];

    for (int task = warp; task < 24; task += 8) {
        if (task < 16) {                       // Q heads
            int h = task;
            const float* src = q + (size_t)tok * (Hn * DHn) + h * 64;
            float x0 = src[lane], x1 = src[lane + 32];
            float ss = x0 * x0 + x1 * x1;
#pragma unroll
            for (int o = 16; o; o >>= 1) ss += __shfl_xor_sync(0xffffffffu, ss, o);
            float r = rsqrtf(ss * (1.0f / 64.0f) + 1e-6f);
            x0 *= r * qn[lane];
            x1 *= r * qn[lane + 32];
            float* dst = qt + (((size_t)(b * Hn + h) * Sn) + s) * 64;
            dst[lane]      = x0 * c0 - x1 * s0;
            dst[lane + 32] = x1 * c1 + x0 * s1;
        } else if (task < 20) {                // K heads
            int h = task - 16;
            const float* src = k + (size_t)tok * (HKVn * DHn) + h * 64;
            float x0 = src[lane], x1 = src[lane + 32];
            float ss = x0 * x0 + x1 * x1;
#pragma unroll
            for (int o = 16; o; o >>= 1) ss += __shfl_xor_sync(0xffffffffu, ss, o);
            float r = rsqrtf(ss * (1.0f / 64.0f) + 1e-6f);
            x0 *= r * kn[lane];
            x1 *= r * kn[lane + 32];
            float* dst = kt + (((size_t)(b * HKVn + h) * Sn) + s) * 64;
            dst[lane]      = x0 * c0 - x1 * s0;
            dst[lane + 32] = x1 * c1 + x0 * s1;
        } else {                               // V heads: transpose copy
            int h = task - 20;
            const float* src = v + (size_t)tok * (HKVn * DHn) + h * 64;
            float* dst = vt + (((size_t)(b * HKVn + h) * Sn) + s) * 64;
            dst[lane]      = src[lane];
            dst[lane + 32] = src[lane + 32];
        }
    }
}

// ============================================================
// Sliding-window attention (|i-j| <= 128), flash-style online softmax.
// Block: 256 threads, 64 queries of one (b,h); key tiles of 32, 10 tiles
// covering [q0-128, q0+192) (aligned, fully in-or-out of [0,S)).
// ============================================================
__global__ __launch_bounds__(256) void attn_kernel(
    const float* __restrict__ qt, const float* __restrict__ kt,
    const float* __restrict__ vt, float* __restrict__ att)
{
    __shared__ float Qs[64 * 64];       // [r][kk], stride 64
    __shared__ float KVs[2112];         // K phase: KT[kk*33+c] ; V phase: V[c*64+d]
    __shared__ float Ss[64 * 33];       // scores/probs, stride 33
    __shared__ float alpha_s[64];

    const int t  = threadIdx.x;
    const int q0 = blockIdx.x * 64;
    const int h  = blockIdx.y;
    const int b  = blockIdx.z;
    const int hk = h >> 2;              // GQA: 4 q-heads per kv-head

    const float* Qg = qt + (((size_t)(b * Hn + h) * Sn) + q0) * 64;
    const float* Kg = kt + ((size_t)(b * HKVn + hk) * Sn) * 64;
    const float* Vg = vt + ((size_t)(b * HKVn + hk) * Sn) * 64;

    for (int i = t * 4; i < 4096; i += 1024)
        *(float4*)(Qs + i) = *(const float4*)(Qg + i);

    const int ty = t >> 4;
    const int tx = t & 15;
    const int r0 = ty * 4;              // 4 query rows
    const int cs = tx * 2;              // 2 score cols
    const int d0 = tx * 4;              // 4 output dims

    float acc[4][4] = {};
    float m_r = -1e30f, l_r = 0.0f;     // valid for t < 64 (row t)

    __syncthreads();

    for (int it = 0; it < 10; it++) {
        const int kbase = q0 - 128 + it * 32;
        if (kbase < 0 || kbase >= Sn) continue;

        // ---- load K tile transposed: KT[kk][c] (stride 33, conflict-free) ----
        const float* Kt = Kg + (size_t)kbase * 64;
        for (int idx = t; idx < 2048; idx += 256) {
            int c = idx >> 6, kk = idx & 63;
            KVs[kk * 33 + c] = Kt[idx];
        }
        __syncthreads();

        // ---- scores: S[r0..r0+3][cs..cs+1] ----
        float sc[4][2] = {};
#pragma unroll
        for (int kk = 0; kk < 64; kk += 4) {
            float qr[4][4];
            *(float4*)qr[0] = *(const float4*)(Qs + (r0 + 0) * 64 + kk);
            *(float4*)qr[1] = *(const float4*)(Qs + (r0 + 1) * 64 + kk);
            *(float4*)qr[2] = *(const float4*)(Qs + (r0 + 2) * 64 + kk);
            *(float4*)qr[3] = *(const float4*)(Qs + (r0 + 3) * 64 + kk);
#pragma unroll
            for (int u = 0; u < 4; u++) {
                float kv0 = KVs[(kk + u) * 33 + cs];
                float kv1 = KVs[(kk + u) * 33 + cs + 1];
#pragma unroll
                for (int ri = 0; ri < 4; ri++) {
                    sc[ri][0] += qr[ri][u] * kv0;
                    sc[ri][1] += qr[ri][u] * kv1;
                }
            }
        }
#pragma unroll
        for (int ri = 0; ri < 4; ri++) {
            Ss[(r0 + ri) * 33 + cs]     = sc[ri][0] * 0.125f;
            Ss[(r0 + ri) * 33 + cs + 1] = sc[ri][1] * 0.125f;
        }
        __syncthreads();

        // ---- per-row online softmax (threads 0..63, row t) ----
        if (t < 64) {
            const int ig = q0 + t;
            float mloc = -1e30f;
#pragma unroll
            for (int c = 0; c < 32; c++) {
                int j = kbase + c;
                float v = Ss[t * 33 + c];
                if (j < ig - 128 || j > ig + 128) v = -1e30f;
                Ss[t * 33 + c] = v;
                mloc = fmaxf(mloc, v);
            }
            float m_new = fmaxf(m_r, mloc);
            float al = __expf(m_r - m_new);   // both -1e30 -> exp(0)=1, acc==0 anyway
            float ls = 0.0f;
#pragma unroll
            for (int c = 0; c < 32; c++) {
                float v = Ss[t * 33 + c];
                float p = (v > -1e29f) ? __expf(v - m_new) : 0.0f;
                Ss[t * 33 + c] = p;
                ls += p;
            }
            l_r = l_r * al + ls;
            m_r = m_new;
            alpha_s[t] = al;
        }
        __syncthreads();

        // ---- rescale accumulators + load V tile (natural layout) ----
        float al0 = alpha_s[r0], al1 = alpha_s[r0 + 1];
        float al2 = alpha_s[r0 + 2], al3 = alpha_s[r0 + 3];
        const float* Vt = Vg + (size_t)kbase * 64;
        for (int i = t * 4; i < 2048; i += 1024)
            *(float4*)(KVs + i) = *(const float4*)(Vt + i);
#pragma unroll
        for (int j = 0; j < 4; j++) {
            acc[0][j] *= al0; acc[1][j] *= al1;
            acc[2][j] *= al2; acc[3][j] *= al3;
        }
        __syncthreads();

        // ---- O += P @ V ----
#pragma unroll 8
        for (int c = 0; c < 32; c++) {
            float vv[4];
            *(float4*)vv = *(const float4*)(KVs + c * 64 + d0);
            float p0 = Ss[(r0 + 0) * 33 + c];
            float p1 = Ss[(r0 + 1) * 33 + c];
            float p2 = Ss[(r0 + 2) * 33 + c];
            float p3 = Ss[(r0 + 3) * 33 + c];
#pragma unroll
            for (int j = 0; j < 4; j++) {
                acc[0][j] += p0 * vv[j];
                acc[1][j] += p1 * vv[j];
                acc[2][j] += p2 * vv[j];
                acc[3][j] += p3 * vv[j];
            }
        }
        __syncthreads();
    }

    if (t < 64) alpha_s[t] = 1.0f / l_r;
    __syncthreads();

#pragma unroll
    for (int ri = 0; ri < 4; ri++) {
        float inv = alpha_s[r0 + ri];
        int row = q0 + r0 + ri;
        float4 o;
        o.x = acc[ri][0] * inv; o.y = acc[ri][1] * inv;
        o.z = acc[ri][2] * inv; o.w = acc[ri][3] * inv;
        *(float4*)(att + ((size_t)(b * Sn + row) * (Hn * DHn)) + h * 64 + d0) = o;
    }
}

// ============================================================
extern "C" void kernel_launch(void* const* d_in, const int* in_sizes, int n_in,
                              void* d_out, int out_size)
{
    const float* x    = (const float*)d_in[0];
    const float* Wq   = (const float*)d_in[1];
    const float* bq   = (const float*)d_in[2];
    const float* Wk   = (const float*)d_in[3];
    const float* bk   = (const float*)d_in[4];
    const float* Wv   = (const float*)d_in[5];
    const float* bv   = (const float*)d_in[6];
    const float* Wo   = (const float*)d_in[7];
    const float* bo   = (const float*)d_in[8];
    const float* qn   = (const float*)d_in[9];
    const float* kn   = (const float*)d_in[10];
    const float* cosT = (const float*)d_in[11];
    const float* sinT = (const float*)d_in[12];
    float* out = (float*)d_out;

    float *gq, *gk, *gv, *gqt, *gkt, *gvt, *gatt;
    cudaGetSymbolAddress((void**)&gq,  g_q);
    cudaGetSymbolAddress((void**)&gk,  g_k);
    cudaGetSymbolAddress((void**)&gv,  g_v);
    cudaGetSymbolAddress((void**)&gqt, g_qt);
    cudaGetSymbolAddress((void**)&gkt, g_kt);
    cudaGetSymbolAddress((void**)&gvt, g_vt);
    cudaGetSymbolAddress((void**)&gatt, g_att);

    // QKV projections
    sgemm_bias_kernel<<<dim3(8, 128), 256>>>(x, Wq, bq, gq, Mtok, 1024, 1024);
    sgemm_bias_kernel<<<dim3(2, 128), 256>>>(x, Wk, bk, gk, Mtok, 256, 1024);
    sgemm_bias_kernel<<<dim3(2, 128), 256>>>(x, Wv, bv, gv, Mtok, 256, 1024);

    // RMSNorm + RoPE + transpose
    norm_rope_kernel<<<Mtok, 256>>>(gq, gk, gv, qn, kn, cosT, sinT, gqt, gkt, gvt);

    // Sliding-window attention
    attn_kernel<<<dim3(Sn / 64, Hn, Bn), 256>>>(gqt, gkt, gvt, gatt);

    // Output projection -> d_out
    sgemm_bias_kernel<<<dim3(8, 128), 256>>>(gatt, Wo, bo, out, Mtok, 1024, 1024);
}

// round 4
// speedup vs baseline: 1.8553x; 1.8553x over previous
#include <cuda_runtime.h>
#include <cuda_fp16.h>
#include <cstdint>

#define Bn   4
#define Sn   4096
#define Dn   1024
#define Hn   16
#define HKVn 4
#define DHn  64
#define Mtok (Bn*Sn)            // 16384

// ---- scratch (static device globals: allowed) ----
__device__ float g_q  [Mtok * Hn   * DHn];
__device__ float g_k  [Mtok * HKVn * DHn];
__device__ float g_v  [Mtok * HKVn * DHn];
__device__ float g_qt [Bn * Hn   * Sn * DHn];
__device__ float g_kt [Bn * HKVn * Sn * DHn];
__device__ float g_vt [Bn * HKVn * Sn * DHn];
__device__ float g_att[Mtok * Hn * DHn];

// fp16 split operands
__device__ __half g_xh [Mtok * Dn];
__device__ __half g_xl [Mtok * Dn];
__device__ __half g_ah [Mtok * Hn * DHn];
__device__ __half g_al [Mtok * Hn * DHn];
__device__ __half g_wqh[Dn * Hn * DHn],   g_wql[Dn * Hn * DHn];    // [N=1024,K=1024]
__device__ __half g_wkh[Dn * HKVn * DHn], g_wkl[Dn * HKVn * DHn];  // [N=256, K=1024]
__device__ __half g_wvh[Dn * HKVn * DHn], g_wvl[Dn * HKVn * DHn];
__device__ __half g_woh[Hn * DHn * Dn],   g_wol[Hn * DHn * Dn];    // [N=1024,K=1024]

// ============================================================
// helpers
// ============================================================
__device__ __forceinline__ uint32_t smem_u32(const void* p) {
    uint32_t a;
    asm("{ .reg .u64 t; cvta.to.shared.u64 t, %1; cvt.u32.u64 %0, t; }" : "=r"(a) : "l"(p));
    return a;
}
__device__ __forceinline__ void cp16(uint32_t dst, const void* src) {
    asm volatile("cp.async.cg.shared.global [%0], [%1], 16;" :: "r"(dst), "l"(src));
}
#define CP_COMMIT() asm volatile("cp.async.commit_group;" ::: "memory")
#define CP_WAIT3()  asm volatile("cp.async.wait_group 3;" ::: "memory")

__device__ __forceinline__ void ldmx4(uint32_t* r, uint32_t addr) {
    asm volatile("ldmatrix.sync.aligned.m8n8.x4.shared.b16 {%0,%1,%2,%3}, [%4];"
        : "=r"(r[0]), "=r"(r[1]), "=r"(r[2]), "=r"(r[3]) : "r"(addr));
}
__device__ __forceinline__ void mma16816(float* c, const uint32_t* a, const uint32_t* b) {
    asm volatile("mma.sync.aligned.m16n8k16.row.col.f32.f16.f16.f32 "
        "{%0,%1,%2,%3}, {%4,%5,%6,%7}, {%8,%9}, {%0,%1,%2,%3};"
        : "+f"(c[0]), "+f"(c[1]), "+f"(c[2]), "+f"(c[3])
        : "r"(a[0]), "r"(a[1]), "r"(a[2]), "r"(a[3]), "r"(b[0]), "r"(b[1]));
}

// ============================================================
// split fp32 -> fp16 hi/lo (elementwise, float4 vectorized)
// ============================================================
__global__ __launch_bounds__(256) void split_kernel(
    const float* __restrict__ s, __half* __restrict__ hi,
    __half* __restrict__ lo, int n4)
{
    int i = blockIdx.x * 256 + threadIdx.x;
    if (i >= n4) return;
    float4 v = ((const float4*)s)[i];
    float vv[4] = {v.x, v.y, v.z, v.w};
    ushort hu[4], lu[4];
#pragma unroll
    for (int j = 0; j < 4; j++) {
        __half h = __float2half_rn(vv[j]);
        __half l = __float2half_rn(vv[j] - __half2float(h));
        hu[j] = __half_as_ushort(h);
        lu[j] = __half_as_ushort(l);
    }
    ((ushort4*)hi)[i] = make_ushort4(hu[0], hu[1], hu[2], hu[3]);
    ((ushort4*)lo)[i] = make_ushort4(lu[0], lu[1], lu[2], lu[3]);
}

// ============================================================
// transpose + split: W[K,N] fp32 -> hi/lo [N,K] fp16
// ============================================================
__global__ __launch_bounds__(256) void tsplit_kernel(
    const float* __restrict__ W, __half* __restrict__ hi,
    __half* __restrict__ lo, int K, int N)
{
    __shared__ float tile[32][33];
    int n0 = blockIdx.x * 32, k0 = blockIdx.y * 32;
    int tx = threadIdx.x, ty = threadIdx.y;      // 32 x 8
    for (int r = ty; r < 32; r += 8)
        tile[r][tx] = W[(size_t)(k0 + r) * N + n0 + tx];
    __syncthreads();
    for (int r = ty; r < 32; r += 8) {
        float v = tile[tx][r];                   // W[k0+tx][n0+r]
        __half h = __float2half_rn(v);
        __half l = __float2half_rn(v - __half2float(h));
        hi[(size_t)(n0 + r) * K + k0 + tx] = h;
        lo[(size_t)(n0 + r) * K + k0 + tx] = l;
    }
}

// ============================================================
// HMMA split GEMM: C[M,N] = A[M,K] @ Bt[N,K]^T + bias
// 128x128 tile, BK=32, 4-stage cp.async pipeline, 8 warps.
// D += Ah*Bh + Al*Bh + Ah*Bl  (fp32 accumulate)
// Smem tile layout: 128 rows x 64B (32 halfs), 16B unit swizzle:
//   phys_col16 = col16 ^ ((row>>1)&3)   (conflict-free for ldmatrix)
// ============================================================
__global__ __launch_bounds__(256, 1) void mm_hmma_kernel(
    const __half* __restrict__ Ah, const __half* __restrict__ Al,
    const __half* __restrict__ Bh, const __half* __restrict__ Bl,
    const float* __restrict__ bias, float* __restrict__ Cm, int N, int K)
{
    extern __shared__ char sm[];
    const int t = threadIdx.x, wid = t >> 5, lane = t & 31;
    const int m0 = blockIdx.y * 128, n0 = blockIdx.x * 128;
    const uint32_t sbase = smem_u32(sm);

    const __half* gAh = Ah + (size_t)m0 * K;
    const __half* gAl = Al + (size_t)m0 * K;
    const __half* gBh = Bh + (size_t)n0 * K;
    const __half* gBl = Bl + (size_t)n0 * K;

    // per-thread load geometry (2 rows per tile per stage)
    const int lr = t >> 2;              // 0..63
    const int lc16 = t & 3;

    // warp tiling: warp_m in 0..3 (rows), warp_n in 0..1 (cols)
    const int warp_m = wid & 3;
    const int warp_n = wid >> 2;

    // A fragment lane geometry (ldmatrix.x4: lanes 0-7 rows 0-7 k0, 8-15 rows 8-15 k0,
    //                            16-23 rows 0-7 k8, 24-31 rows 8-15 k8)
    const int a_row = warp_m * 32 + (lane & 15);
    const int a_k8  = lane >> 4;
    // B fragment lane geometry (lanes 0-7 n0-7 k0, 8-15 n0-7 k8, 16-23 n8-15 k0, 24-31 n8-15 k8)
    const int b_row = warp_n * 64 + (lane & 7) + ((lane >> 4) << 3);
    const int b_k8  = (lane >> 3) & 1;

    float acc[2][8][4];
#pragma unroll
    for (int a = 0; a < 2; a++)
#pragma unroll
        for (int b = 0; b < 8; b++)
#pragma unroll
            for (int cq = 0; cq < 4; cq++) acc[a][b][cq] = 0.0f;

    const int NCH = K >> 5;

    // ---- stage loader ----
#define STAGE_LOAD(s, c) do { \
    uint32_t sb_ = sbase + (uint32_t)(s) * 32768u; \
    _Pragma("unroll") \
    for (int i_ = 0; i_ < 2; i_++) { \
        int row_ = i_ * 64 + lr; \
        uint32_t sw_ = (uint32_t)row_ * 64u + (uint32_t)((lc16 ^ ((row_ >> 1) & 3)) << 4); \
        size_t go_ = (size_t)row_ * K + (size_t)(c) * 32 + lc16 * 8; \
        cp16(sb_ + sw_,          gAh + go_); \
        cp16(sb_ + 8192u + sw_,  gAl + go_); \
        cp16(sb_ + 16384u + sw_, gBh + go_); \
        cp16(sb_ + 24576u + sw_, gBl + go_); \
    } } while (0)

    // prologue: fill 4 stages
#pragma unroll
    for (int s = 0; s < 4; s++) { STAGE_LOAD(s, s); CP_COMMIT(); }

    for (int c = 0; c < NCH; c++) {
        CP_WAIT3();
        __syncthreads();

        const uint32_t sb = sbase + (uint32_t)(c & 3) * 32768u;
#pragma unroll
        for (int ks = 0; ks < 2; ks++) {
            uint32_t ah[2][4], al[2][4], bh[4][4], bl[4][4];
#pragma unroll
            for (int mt = 0; mt < 2; mt++) {
                int r = a_row + mt * 16;
                uint32_t ad = sb + (uint32_t)r * 64u +
                              (uint32_t)(((ks * 2 + a_k8) ^ ((r >> 1) & 3)) << 4);
                ldmx4(ah[mt], ad);
                ldmx4(al[mt], ad + 8192u);
            }
#pragma unroll
            for (int g = 0; g < 4; g++) {
                int r = b_row + g * 16;
                uint32_t bd = sb + 16384u + (uint32_t)r * 64u +
                              (uint32_t)(((ks * 2 + b_k8) ^ ((r >> 1) & 3)) << 4);
                ldmx4(bh[g], bd);
                ldmx4(bl[g], bd + 8192u);
            }
#pragma unroll
            for (int mt = 0; mt < 2; mt++)
#pragma unroll
                for (int j = 0; j < 8; j++)
                    mma16816(acc[mt][j], ah[mt], &bh[j >> 1][(j & 1) * 2]);
#pragma unroll
            for (int mt = 0; mt < 2; mt++)
#pragma unroll
                for (int j = 0; j < 8; j++)
                    mma16816(acc[mt][j], al[mt], &bh[j >> 1][(j & 1) * 2]);
#pragma unroll
            for (int mt = 0; mt < 2; mt++)
#pragma unroll
                for (int j = 0; j < 8; j++)
                    mma16816(acc[mt][j], ah[mt], &bl[j >> 1][(j & 1) * 2]);
        }
        __syncthreads();
        if (c + 4 < NCH) STAGE_LOAD(c & 3, c + 4);
        CP_COMMIT();
    }
#undef STAGE_LOAD

    // epilogue
    const int crow = m0 + warp_m * 32 + (lane >> 2);
    const int ccol = n0 + warp_n * 64 + (lane & 3) * 2;
#pragma unroll
    for (int j = 0; j < 8; j++) {
        int col = ccol + j * 8;
        float b0 = bias[col], b1 = bias[col + 1];
#pragma unroll
        for (int mt = 0; mt < 2; mt++) {
            int r0 = crow + mt * 16;
            float2 o0 = make_float2(acc[mt][j][0] + b0, acc[mt][j][1] + b1);
            float2 o1 = make_float2(acc[mt][j][2] + b0, acc[mt][j][3] + b1);
            *(float2*)(Cm + (size_t)r0 * N + col)       = o0;
            *(float2*)(Cm + (size_t)(r0 + 8) * N + col) = o1;
        }
    }
}

// ============================================================
// RMSNorm + RoPE + transpose (unchanged from passing R2)
// ============================================================
__global__ __launch_bounds__(256) void norm_rope_kernel(
    const float* __restrict__ q, const float* __restrict__ k, const float* __restrict__ v,
    const float* __restrict__ qn, const float* __restrict__ kn,
    const float* __restrict__ cosT, const float* __restrict__ sinT,
    float* __restrict__ qt, float* __restrict__ kt, float* __restrict__ vt)
{
    const int tok  = blockIdx.x;
    const int b    = tok >> 12;
    const int s    = tok & 4095;
    const int warp = threadIdx.x >> 5;
    const int lane = threadIdx.x & 31;

    const float c0 = cosT[s * 64 + lane];
    const float c1 = cosT[s * 64 + lane + 32];
    const float s0 = sinT[s * 64 + lane];
    const float s1 = sinT[s * 64 + lane + 32];

    for (int task = warp; task < 24; task += 8) {
        if (task < 16) {
            int h = task;
            const float* src = q + (size_t)tok * (Hn * DHn) + h * 64;
            float x0 = src[lane], x1 = src[lane + 32];
            float ss = x0 * x0 + x1 * x1;
#pragma unroll
            for (int o = 16; o; o >>= 1) ss += __shfl_xor_sync(0xffffffffu, ss, o);
            float r = rsqrtf(ss * (1.0f / 64.0f) + 1e-6f);
            x0 *= r * qn[lane];
            x1 *= r * qn[lane + 32];
            float* dst = qt + (((size_t)(b * Hn + h) * Sn) + s) * 64;
            dst[lane]      = x0 * c0 - x1 * s0;
            dst[lane + 32] = x1 * c1 + x0 * s1;
        } else if (task < 20) {
            int h = task - 16;
            const float* src = k + (size_t)tok * (HKVn * DHn) + h * 64;
            float x0 = src[lane], x1 = src[lane + 32];
            float ss = x0 * x0 + x1 * x1;
#pragma unroll
            for (int o = 16; o; o >>= 1) ss += __shfl_xor_sync(0xffffffffu, ss, o);
            float r = rsqrtf(ss * (1.0f / 64.0f) + 1e-6f);
            x0 *= r * kn[lane];
            x1 *= r * kn[lane + 32];
            float* dst = kt + (((size_t)(b * HKVn + h) * Sn) + s) * 64;
            dst[lane]      = x0 * c0 - x1 * s0;
            dst[lane + 32] = x1 * c1 + x0 * s1;
        } else {
            int h = task - 20;
            const float* src = v + (size_t)tok * (HKVn * DHn) + h * 64;
            float* dst = vt + (((size_t)(b * HKVn + h) * Sn) + s) * 64;
            dst[lane]      = src[lane];
            dst[lane + 32] = src[lane + 32];
        }
    }
}

// ============================================================
// Sliding-window attention (unchanged from passing R2)
// ============================================================
__global__ __launch_bounds__(256) void attn_kernel(
    const float* __restrict__ qt, const float* __restrict__ kt,
    const float* __restrict__ vt, float* __restrict__ att)
{
    __shared__ float Qs[64 * 64];
    __shared__ float KVs[2112];
    __shared__ float Ss[64 * 33];
    __shared__ float alpha_s[64];

    const int t  = threadIdx.x;
    const int q0 = blockIdx.x * 64;
    const int h  = blockIdx.y;
    const int b  = blockIdx.z;
    const int hk = h >> 2;

    const float* Qg = qt + (((size_t)(b * Hn + h) * Sn) + q0) * 64;
    const float* Kg = kt + ((size_t)(b * HKVn + hk) * Sn) * 64;
    const float* Vg = vt + ((size_t)(b * HKVn + hk) * Sn) * 64;

    for (int i = t * 4; i < 4096; i += 1024)
        *(float4*)(Qs + i) = *(const float4*)(Qg + i);

    const int ty = t >> 4;
    const int tx = t & 15;
    const int r0 = ty * 4;
    const int cs = tx * 2;
    const int d0 = tx * 4;

    float acc[4][4] = {};
    float m_r = -1e30f, l_r = 0.0f;

    __syncthreads();

    for (int it = 0; it < 10; it++) {
        const int kbase = q0 - 128 + it * 32;
        if (kbase < 0 || kbase >= Sn) continue;

        const float* Kt = Kg + (size_t)kbase * 64;
        for (int idx = t; idx < 2048; idx += 256) {
            int c = idx >> 6, kk = idx & 63;
            KVs[kk * 33 + c] = Kt[idx];
        }
        __syncthreads();

        float sc[4][2] = {};
#pragma unroll
        for (int kk = 0; kk < 64; kk += 4) {
            float qr[4][4];
            *(float4*)qr[0] = *(const float4*)(Qs + (r0 + 0) * 64 + kk);
            *(float4*)qr[1] = *(const float4*)(Qs + (r0 + 1) * 64 + kk);
            *(float4*)qr[2] = *(const float4*)(Qs + (r0 + 2) * 64 + kk);
            *(float4*)qr[3] = *(const float4*)(Qs + (r0 + 3) * 64 + kk);
#pragma unroll
            for (int u = 0; u < 4; u++) {
                float kv0 = KVs[(kk + u) * 33 + cs];
                float kv1 = KVs[(kk + u) * 33 + cs + 1];
#pragma unroll
                for (int ri = 0; ri < 4; ri++) {
                    sc[ri][0] += qr[ri][u] * kv0;
                    sc[ri][1] += qr[ri][u] * kv1;
                }
            }
        }
#pragma unroll
        for (int ri = 0; ri < 4; ri++) {
            Ss[(r0 + ri) * 33 + cs]     = sc[ri][0] * 0.125f;
            Ss[(r0 + ri) * 33 + cs + 1] = sc[ri][1] * 0.125f;
        }
        __syncthreads();

        if (t < 64) {
            const int ig = q0 + t;
            float mloc = -1e30f;
#pragma unroll
            for (int c = 0; c < 32; c++) {
                int j = kbase + c;
                float v = Ss[t * 33 + c];
                if (j < ig - 128 || j > ig + 128) v = -1e30f;
                Ss[t * 33 + c] = v;
                mloc = fmaxf(mloc, v);
            }
            float m_new = fmaxf(m_r, mloc);
            float al = __expf(m_r - m_new);
            float ls = 0.0f;
#pragma unroll
            for (int c = 0; c < 32; c++) {
                float v = Ss[t * 33 + c];
                float p = (v > -1e29f) ? __expf(v - m_new) : 0.0f;
                Ss[t * 33 + c] = p;
                ls += p;
            }
            l_r = l_r * al + ls;
            m_r = m_new;
            alpha_s[t] = al;
        }
        __syncthreads();

        float al0 = alpha_s[r0], al1 = alpha_s[r0 + 1];
        float al2 = alpha_s[r0 + 2], al3 = alpha_s[r0 + 3];
        const float* Vt = Vg + (size_t)kbase * 64;
        for (int i = t * 4; i < 2048; i += 1024)
            *(float4*)(KVs + i) = *(const float4*)(Vt + i);
#pragma unroll
        for (int j = 0; j < 4; j++) {
            acc[0][j] *= al0; acc[1][j] *= al1;
            acc[2][j] *= al2; acc[3][j] *= al3;
        }
        __syncthreads();

#pragma unroll 8
        for (int c = 0; c < 32; c++) {
            float vv[4];
            *(float4*)vv = *(const float4*)(KVs + c * 64 + d0);
            float p0 = Ss[(r0 + 0) * 33 + c];
            float p1 = Ss[(r0 + 1) * 33 + c];
            float p2 = Ss[(r0 + 2) * 33 + c];
            float p3 = Ss[(r0 + 3) * 33 + c];
#pragma unroll
            for (int j = 0; j < 4; j++) {
                acc[0][j] += p0 * vv[j];
                acc[1][j] += p1 * vv[j];
                acc[2][j] += p2 * vv[j];
                acc[3][j] += p3 * vv[j];
            }
        }
        __syncthreads();
    }

    if (t < 64) alpha_s[t] = 1.0f / l_r;
    __syncthreads();

#pragma unroll
    for (int ri = 0; ri < 4; ri++) {
        float inv = alpha_s[r0 + ri];
        int row = q0 + r0 + ri;
        float4 o;
        o.x = acc[ri][0] * inv; o.y = acc[ri][1] * inv;
        o.z = acc[ri][2] * inv; o.w = acc[ri][3] * inv;
        *(float4*)(att + ((size_t)(b * Sn + row) * (Hn * DHn)) + h * 64 + d0) = o;
    }
}

// ============================================================
extern "C" void kernel_launch(void* const* d_in, const int* in_sizes, int n_in,
                              void* d_out, int out_size)
{
    const float* x    = (const float*)d_in[0];
    const float* Wq   = (const float*)d_in[1];
    const float* bq   = (const float*)d_in[2];
    const float* Wk   = (const float*)d_in[3];
    const float* bk   = (const float*)d_in[4];
    const float* Wv   = (const float*)d_in[5];
    const float* bv   = (const float*)d_in[6];
    const float* Wo   = (const float*)d_in[7];
    const float* bo   = (const float*)d_in[8];
    const float* qn   = (const float*)d_in[9];
    const float* kn   = (const float*)d_in[10];
    const float* cosT = (const float*)d_in[11];
    const float* sinT = (const float*)d_in[12];
    float* out = (float*)d_out;

    float *gq, *gk, *gv, *gqt, *gkt, *gvt, *gatt;
    __half *xh, *xl, *ah, *al, *wqh, *wql, *wkh, *wkl, *wvh, *wvl, *woh, *wol;
    cudaGetSymbolAddress((void**)&gq,  g_q);
    cudaGetSymbolAddress((void**)&gk,  g_k);
    cudaGetSymbolAddress((void**)&gv,  g_v);
    cudaGetSymbolAddress((void**)&gqt, g_qt);
    cudaGetSymbolAddress((void**)&gkt, g_kt);
    cudaGetSymbolAddress((void**)&gvt, g_vt);
    cudaGetSymbolAddress((void**)&gatt, g_att);
    cudaGetSymbolAddress((void**)&xh,  g_xh);
    cudaGetSymbolAddress((void**)&xl,  g_xl);
    cudaGetSymbolAddress((void**)&ah,  g_ah);
    cudaGetSymbolAddress((void**)&al,  g_al);
    cudaGetSymbolAddress((void**)&wqh, g_wqh);
    cudaGetSymbolAddress((void**)&wql, g_wql);
    cudaGetSymbolAddress((void**)&wkh, g_wkh);
    cudaGetSymbolAddress((void**)&wkl, g_wkl);
    cudaGetSymbolAddress((void**)&wvh, g_wvh);
    cudaGetSymbolAddress((void**)&wvl, g_wvl);
    cudaGetSymbolAddress((void**)&woh, g_woh);
    cudaGetSymbolAddress((void**)&wol, g_wol);

    cudaFuncSetAttribute(mm_hmma_kernel,
                         cudaFuncAttributeMaxDynamicSharedMemorySize, 131072);
    const int DSMEM = 131072;

    // split activations + weights to fp16 hi/lo
    const int n4x = Mtok * Dn / 4;
    split_kernel<<<(n4x + 255) / 256, 256>>>(x, xh, xl, n4x);
    tsplit_kernel<<<dim3(1024 / 32, 1024 / 32), dim3(32, 8)>>>(Wq, wqh, wql, 1024, 1024);
    tsplit_kernel<<<dim3(256  / 32, 1024 / 32), dim3(32, 8)>>>(Wk, wkh, wkl, 1024, 256);
    tsplit_kernel<<<dim3(256  / 32, 1024 / 32), dim3(32, 8)>>>(Wv, wvh, wvl, 1024, 256);
    tsplit_kernel<<<dim3(1024 / 32, 1024 / 32), dim3(32, 8)>>>(Wo, woh, wol, 1024, 1024);

    // QKV projections (HMMA)
    mm_hmma_kernel<<<dim3(8, 128), 256, DSMEM>>>(xh, xl, wqh, wql, bq, gq, 1024, 1024);
    mm_hmma_kernel<<<dim3(2, 128), 256, DSMEM>>>(xh, xl, wkh, wkl, bk, gk, 256, 1024);
    mm_hmma_kernel<<<dim3(2, 128), 256, DSMEM>>>(xh, xl, wvh, wvl, bv, gv, 256, 1024);

    // RMSNorm + RoPE + transpose
    norm_rope_kernel<<<Mtok, 256>>>(gq, gk, gv, qn, kn, cosT, sinT, gqt, gkt, gvt);

    // Sliding-window attention
    attn_kernel<<<dim3(Sn / 64, Hn, Bn), 256>>>(gqt, gkt, gvt, gatt);

    // Output projection (HMMA) -> d_out
    const int n4a = Mtok * Hn * DHn / 4;
    split_kernel<<<(n4a + 255) / 256, 256>>>(gatt, ah, al, n4a);
    mm_hmma_kernel<<<dim3(8, 128), 256, DSMEM>>>(ah, al, woh, wol, bo, out, 1024, 1024);
}

// round 5
// speedup vs baseline: 6.2690x; 3.3789x over previous
#include <cuda_runtime.h>
#include <cuda_fp16.h>
#include <cstdint>

#define Bn   4
#define Sn   4096
#define Dn   1024
#define Hn   16
#define HKVn 4
#define DHn  64
#define Mtok (Bn*Sn)            // 16384

// ---- scratch (static device globals: allowed) ----
__device__ float g_q  [Mtok * Hn   * DHn];
__device__ float g_k  [Mtok * HKVn * DHn];
__device__ float g_v  [Mtok * HKVn * DHn];

__device__ __half g_xh [Mtok * Dn];                 // x in fp16
__device__ __half g_qh [Bn * Hn   * Sn * DHn];      // normed+roped fp16
__device__ __half g_kh [Bn * HKVn * Sn * DHn];
__device__ __half g_vh [Bn * HKVn * Sn * DHn];
__device__ __half g_ah [Mtok * Hn * DHn];           // attention out fp16 [tok][1024]
__device__ __half g_wq [Dn * Hn * DHn];             // [N,K] fp16
__device__ __half g_wk [Dn * HKVn * DHn];
__device__ __half g_wv [Dn * HKVn * DHn];
__device__ __half g_wo [Hn * DHn * Dn];

// ============================================================
// helpers
// ============================================================
__device__ __forceinline__ uint32_t smem_u32(const void* p) {
    uint32_t a;
    asm("{ .reg .u64 t; cvta.to.shared.u64 t, %1; cvt.u32.u64 %0, t; }" : "=r"(a) : "l"(p));
    return a;
}
__device__ __forceinline__ void cp16(uint32_t dst, const void* src) {
    asm volatile("cp.async.cg.shared.global [%0], [%1], 16;" :: "r"(dst), "l"(src));
}
#define CP_COMMIT() asm volatile("cp.async.commit_group;" ::: "memory")
#define CP_WAIT0()  asm volatile("cp.async.wait_group 0;" ::: "memory")
#define CP_WAIT1()  asm volatile("cp.async.wait_group 1;" ::: "memory")
#define CP_WAIT3()  asm volatile("cp.async.wait_group 3;" ::: "memory")

__device__ __forceinline__ void ldmx4(uint32_t* r, uint32_t addr) {
    asm volatile("ldmatrix.sync.aligned.m8n8.x4.shared.b16 {%0,%1,%2,%3}, [%4];"
        : "=r"(r[0]), "=r"(r[1]), "=r"(r[2]), "=r"(r[3]) : "r"(addr));
}
__device__ __forceinline__ void ldmx4t(uint32_t* r, uint32_t addr) {
    asm volatile("ldmatrix.sync.aligned.m8n8.x4.trans.shared.b16 {%0,%1,%2,%3}, [%4];"
        : "=r"(r[0]), "=r"(r[1]), "=r"(r[2]), "=r"(r[3]) : "r"(addr));
}
__device__ __forceinline__ void mma16816(float* c, const uint32_t* a, const uint32_t* b) {
    asm volatile("mma.sync.aligned.m16n8k16.row.col.f32.f16.f16.f32 "
        "{%0,%1,%2,%3}, {%4,%5,%6,%7}, {%8,%9}, {%0,%1,%2,%3};"
        : "+f"(c[0]), "+f"(c[1]), "+f"(c[2]), "+f"(c[3])
        : "r"(a[0]), "r"(a[1]), "r"(a[2]), "r"(a[3]), "r"(b[0]), "r"(b[1]));
}
__device__ __forceinline__ uint32_t pack_h2(float a, float b) {
    __half2 h = __floats2half2_rn(a, b);
    return *reinterpret_cast<uint32_t*>(&h);
}

// ============================================================
// convert fp32 -> fp16 (float4 vectorized)
// ============================================================
__global__ __launch_bounds__(256) void cvt_kernel(
    const float* __restrict__ s, __half* __restrict__ d, int n4)
{
    int i = blockIdx.x * 256 + threadIdx.x;
    if (i >= n4) return;
    float4 v = ((const float4*)s)[i];
    ushort4 o;
    o.x = __half_as_ushort(__float2half_rn(v.x));
    o.y = __half_as_ushort(__float2half_rn(v.y));
    o.z = __half_as_ushort(__float2half_rn(v.z));
    o.w = __half_as_ushort(__float2half_rn(v.w));
    ((ushort4*)d)[i] = o;
}

// ============================================================
// transpose + convert: W[K,N] fp32 -> [N,K] fp16
// ============================================================
__global__ __launch_bounds__(256) void tcvt_kernel(
    const float* __restrict__ W, __half* __restrict__ o, int K, int N)
{
    __shared__ float tile[32][33];
    int n0 = blockIdx.x * 32, k0 = blockIdx.y * 32;
    int tx = threadIdx.x, ty = threadIdx.y;      // 32 x 8
    for (int r = ty; r < 32; r += 8)
        tile[r][tx] = W[(size_t)(k0 + r) * N + n0 + tx];
    __syncthreads();
    for (int r = ty; r < 32; r += 8)
        o[(size_t)(n0 + r) * K + k0 + tx] = __float2half_rn(tile[tx][r]);
}

// ============================================================
// HMMA GEMM: C[M,N] = A[M,K] @ Bt[N,K]^T + bias  (fp16 in, fp32 out)
// 128x128 tile, BK=32, 4-stage cp.async pipeline, 8 warps, 2 CTA/SM.
// ============================================================
__global__ __launch_bounds__(256, 2) void mm_hmma_kernel(
    const __half* __restrict__ Ah, const __half* __restrict__ Bh,
    const float* __restrict__ bias, float* __restrict__ Cm, int N, int K)
{
    extern __shared__ char sm[];
    const int t = threadIdx.x, wid = t >> 5, lane = t & 31;
    const int m0 = blockIdx.y * 128, n0 = blockIdx.x * 128;
    const uint32_t sbase = smem_u32(sm);

    const __half* gA = Ah + (size_t)m0 * K;
    const __half* gB = Bh + (size_t)n0 * K;

    const int lr = t >> 2;              // 0..63
    const int lc16 = t & 3;

    const int warp_m = wid & 3;
    const int warp_n = wid >> 2;

    const int a_row = warp_m * 32 + (lane & 15);
    const int a_k8  = lane >> 4;
    const int b_row = warp_n * 64 + (lane & 7) + ((lane >> 4) << 3);
    const int b_k8  = (lane >> 3) & 1;

    float acc[2][8][4];
#pragma unroll
    for (int a = 0; a < 2; a++)
#pragma unroll
        for (int b = 0; b < 8; b++)
#pragma unroll
            for (int cq = 0; cq < 4; cq++) acc[a][b][cq] = 0.0f;

    const int NCH = K >> 5;

#define STAGE_LOAD(s, c) do { \
    uint32_t sb_ = sbase + (uint32_t)(s) * 16384u; \
    _Pragma("unroll") \
    for (int i_ = 0; i_ < 2; i_++) { \
        int row_ = i_ * 64 + lr; \
        uint32_t sw_ = (uint32_t)row_ * 64u + (uint32_t)((lc16 ^ ((row_ >> 1) & 3)) << 4); \
        size_t go_ = (size_t)row_ * K + (size_t)(c) * 32 + lc16 * 8; \
        cp16(sb_ + sw_,         gA + go_); \
        cp16(sb_ + 8192u + sw_, gB + go_); \
    } } while (0)

#pragma unroll
    for (int s = 0; s < 4; s++) { STAGE_LOAD(s, s); CP_COMMIT(); }

    for (int c = 0; c < NCH; c++) {
        CP_WAIT3();
        __syncthreads();

        const uint32_t sb = sbase + (uint32_t)(c & 3) * 16384u;
#pragma unroll
        for (int ks = 0; ks < 2; ks++) {
            uint32_t ah[2][4], bh[4][4];
#pragma unroll
            for (int mt = 0; mt < 2; mt++) {
                int r = a_row + mt * 16;
                uint32_t ad = sb + (uint32_t)r * 64u +
                              (uint32_t)(((ks * 2 + a_k8) ^ ((r >> 1) & 3)) << 4);
                ldmx4(ah[mt], ad);
            }
#pragma unroll
            for (int g = 0; g < 4; g++) {
                int r = b_row + g * 16;
                uint32_t bd = sb + 8192u + (uint32_t)r * 64u +
                              (uint32_t)(((ks * 2 + b_k8) ^ ((r >> 1) & 3)) << 4);
                ldmx4(bh[g], bd);
            }
#pragma unroll
            for (int mt = 0; mt < 2; mt++)
#pragma unroll
                for (int j = 0; j < 8; j++)
                    mma16816(acc[mt][j], ah[mt], &bh[j >> 1][(j & 1) * 2]);
        }
        __syncthreads();
        if (c + 4 < NCH) STAGE_LOAD(c & 3, c + 4);
        CP_COMMIT();
    }
#undef STAGE_LOAD

    const int crow = m0 + warp_m * 32 + (lane >> 2);
    const int ccol = n0 + warp_n * 64 + (lane & 3) * 2;
#pragma unroll
    for (int j = 0; j < 8; j++) {
        int col = ccol + j * 8;
        float b0 = bias[col], b1 = bias[col + 1];
#pragma unroll
        for (int mt = 0; mt < 2; mt++) {
            int r0 = crow + mt * 16;
            float2 o0 = make_float2(acc[mt][j][0] + b0, acc[mt][j][1] + b1);
            float2 o1 = make_float2(acc[mt][j][2] + b0, acc[mt][j][3] + b1);
            *(float2*)(Cm + (size_t)r0 * N + col)       = o0;
            *(float2*)(Cm + (size_t)(r0 + 8) * N + col) = o1;
        }
    }
}

// ============================================================
// RMSNorm + RoPE + transpose -> fp16 [b][h][s][dh]
// ============================================================
__global__ __launch_bounds__(256) void norm_rope_kernel(
    const float* __restrict__ q, const float* __restrict__ k, const float* __restrict__ v,
    const float* __restrict__ qn, const float* __restrict__ kn,
    const float* __restrict__ cosT, const float* __restrict__ sinT,
    __half* __restrict__ qt, __half* __restrict__ kt, __half* __restrict__ vt)
{
    const int tok  = blockIdx.x;
    const int b    = tok >> 12;
    const int s    = tok & 4095;
    const int warp = threadIdx.x >> 5;
    const int lane = threadIdx.x & 31;

    const float c0 = cosT[s * 64 + lane];
    const float c1 = cosT[s * 64 + lane + 32];
    const float s0 = sinT[s * 64 + lane];
    const float s1 = sinT[s * 64 + lane + 32];

    for (int task = warp; task < 24; task += 8) {
        if (task < 16) {
            int h = task;
            const float* src = q + (size_t)tok * (Hn * DHn) + h * 64;
            float x0 = src[lane], x1 = src[lane + 32];
            float ss = x0 * x0 + x1 * x1;
#pragma unroll
            for (int o = 16; o; o >>= 1) ss += __shfl_xor_sync(0xffffffffu, ss, o);
            float r = rsqrtf(ss * (1.0f / 64.0f) + 1e-6f);
            x0 *= r * qn[lane];
            x1 *= r * qn[lane + 32];
            __half* dst = qt + (((size_t)(b * Hn + h) * Sn) + s) * 64;
            dst[lane]      = __float2half_rn(x0 * c0 - x1 * s0);
            dst[lane + 32] = __float2half_rn(x1 * c1 + x0 * s1);
        } else if (task < 20) {
            int h = task - 16;
            const float* src = k + (size_t)tok * (HKVn * DHn) + h * 64;
            float x0 = src[lane], x1 = src[lane + 32];
            float ss = x0 * x0 + x1 * x1;
#pragma unroll
            for (int o = 16; o; o >>= 1) ss += __shfl_xor_sync(0xffffffffu, ss, o);
            float r = rsqrtf(ss * (1.0f / 64.0f) + 1e-6f);
            x0 *= r * kn[lane];
            x1 *= r * kn[lane + 32];
            __half* dst = kt + (((size_t)(b * HKVn + h) * Sn) + s) * 64;
            dst[lane]      = __float2half_rn(x0 * c0 - x1 * s0);
            dst[lane + 32] = __float2half_rn(x1 * c1 + x0 * s1);
        } else {
            int h = task - 20;
            const float* src = v + (size_t)tok * (HKVn * DHn) + h * 64;
            __half* dst = vt + (((size_t)(b * HKVn + h) * Sn) + s) * 64;
            dst[lane]      = __float2half_rn(src[lane]);
            dst[lane + 32] = __float2half_rn(src[lane + 32]);
        }
    }
}

// ============================================================
// HMMA sliding-window flash attention.
// CTA: 128 threads (4 warps), 64 queries of one (b,h).
// Key tiles of 64, covering [q0-128, q0+192), whole tiles in [0,S) only.
// Warp w: query rows [q0+16w, q0+16w+16). Online softmax on fragments.
// smem tiles (64x64 half, 128B rows, SW128 swizzle c16 ^= row&7).
// ============================================================
__global__ __launch_bounds__(128) void attn_mma_kernel(
    const __half* __restrict__ qh, const __half* __restrict__ kh,
    const __half* __restrict__ vh, __half* __restrict__ att)
{
    __shared__ __half Qs[64 * 64];
    __shared__ __half Ks[2][64 * 64];
    __shared__ __half Vs[2][64 * 64];

    const int t = threadIdx.x, wm = t >> 5, lane = t & 31;
    const int q0 = blockIdx.x * 64;
    const int h  = blockIdx.y;
    const int b  = blockIdx.z;
    const int hk = h >> 2;

    const __half* Qg = qh + (((size_t)(b * Hn + h) * Sn) + q0) * 64;
    const __half* Kg = kh + ((size_t)(b * HKVn + hk) * Sn) * 64;
    const __half* Vg = vh + ((size_t)(b * HKVn + hk) * Sn) * 64;

    const uint32_t sQ = smem_u32(Qs);
    const uint32_t sK = smem_u32(Ks);
    const uint32_t sV = smem_u32(Vs);

    // Q tile load (512 x 16B)
    for (int i = t; i < 512; i += 128) {
        int row = i >> 3, c = i & 7;
        uint32_t sw = (uint32_t)row * 128u + (uint32_t)((c ^ (row & 7)) << 4);
        cp16(sQ + sw, Qg + row * 64 + c * 8);
    }

    int lo = 0; while (q0 - 128 + lo * 64 < 0) lo++;
    int hi = 4; while (q0 - 128 + hi * 64 + 64 > Sn) hi--;

#define PREFETCH(it, buf) do { \
    int kb_ = q0 - 128 + (it) * 64; \
    const __half* Kt_ = Kg + (size_t)kb_ * 64; \
    const __half* Vt_ = Vg + (size_t)kb_ * 64; \
    uint32_t sk_ = sK + (uint32_t)(buf) * 8192u; \
    uint32_t sv_ = sV + (uint32_t)(buf) * 8192u; \
    for (int i_ = t; i_ < 512; i_ += 128) { \
        int row_ = i_ >> 3, c_ = i_ & 7; \
        uint32_t sw_ = (uint32_t)row_ * 128u + (uint32_t)((c_ ^ (row_ & 7)) << 4); \
        cp16(sk_ + sw_, Kt_ + row_ * 64 + c_ * 8); \
        cp16(sv_ + sw_, Vt_ + row_ * 64 + c_ * 8); \
    } } while (0)

    PREFETCH(lo, 0);
    CP_COMMIT();

    // fragment lane geometry
    const int arow = wm * 16 + (lane & 15);
    const int ak8  = lane >> 4;
    const int brow = (lane & 7) + ((lane >> 4) << 3);   // K: rows; lanes16-31 -> +8 rows
    const int bk8  = (lane >> 3) & 1;                   // K: lanes 8-15 -> k+8
    const int vrow = (lane & 7) + (((lane >> 3) & 1) << 3);  // V(trans): lanes 8-15 -> +8 rows
    const int vc8  = lane >> 4;                              // V: lanes 16-31 -> col+8

    const int r0g = q0 + wm * 16 + (lane >> 2);   // global query row (low half)
    const int r1g = r0g + 8;

    float acc[8][4];
#pragma unroll
    for (int g = 0; g < 8; g++)
#pragma unroll
        for (int e = 0; e < 4; e++) acc[g][e] = 0.0f;
    float m0 = -1e30f, m1 = -1e30f, l0 = 0.0f, l1 = 0.0f;

    uint32_t qf[4][4];
    bool qloaded = false;

    for (int it = lo; it <= hi; ++it) {
        const int buf = (it - lo) & 1;
        if (it < hi) { PREFETCH(it + 1, buf ^ 1); CP_COMMIT(); CP_WAIT1(); }
        else { CP_WAIT0(); }
        __syncthreads();

        if (!qloaded) {
#pragma unroll
            for (int kblk = 0; kblk < 4; kblk++) {
                uint32_t ad = sQ + (uint32_t)arow * 128u +
                              (uint32_t)(((kblk * 2 + ak8) ^ (arow & 7)) << 4);
                ldmx4(qf[kblk], ad);
            }
            qloaded = true;
        }

        const int kb = q0 - 128 + it * 64;
        const uint32_t sk = sK + (uint32_t)buf * 8192u;
        const uint32_t sv = sV + (uint32_t)buf * 8192u;

        // ---- scores S = Q K^T ----
        float sc[8][4];
#pragma unroll
        for (int g = 0; g < 8; g++)
#pragma unroll
            for (int e = 0; e < 4; e++) sc[g][e] = 0.0f;
#pragma unroll
        for (int kblk = 0; kblk < 4; kblk++) {
#pragma unroll
            for (int g = 0; g < 4; g++) {
                int r = g * 16 + brow;
                uint32_t bd = sk + (uint32_t)r * 128u +
                              (uint32_t)(((kblk * 2 + bk8) ^ (r & 7)) << 4);
                uint32_t bf[4];
                ldmx4(bf, bd);
                mma16816(sc[2 * g],     qf[kblk], bf);
                mma16816(sc[2 * g + 1], qf[kblk], bf + 2);
            }
        }

        // ---- scale + window mask ----
#pragma unroll
        for (int g = 0; g < 8; g++) {
            int j0 = kb + g * 8 + (lane & 3) * 2;
            int j1 = j0 + 1;
            sc[g][0] = (abs(j0 - r0g) <= 128) ? sc[g][0] * 0.125f : -1e30f;
            sc[g][1] = (abs(j1 - r0g) <= 128) ? sc[g][1] * 0.125f : -1e30f;
            sc[g][2] = (abs(j0 - r1g) <= 128) ? sc[g][2] * 0.125f : -1e30f;
            sc[g][3] = (abs(j1 - r1g) <= 128) ? sc[g][3] * 0.125f : -1e30f;
        }

        // ---- row max (over 16 local + 4-lane quad) ----
        float mx0 = -1e30f, mx1 = -1e30f;
#pragma unroll
        for (int g = 0; g < 8; g++) {
            mx0 = fmaxf(mx0, fmaxf(sc[g][0], sc[g][1]));
            mx1 = fmaxf(mx1, fmaxf(sc[g][2], sc[g][3]));
        }
        mx0 = fmaxf(mx0, __shfl_xor_sync(0xffffffffu, mx0, 1));
        mx0 = fmaxf(mx0, __shfl_xor_sync(0xffffffffu, mx0, 2));
        mx1 = fmaxf(mx1, __shfl_xor_sync(0xffffffffu, mx1, 1));
        mx1 = fmaxf(mx1, __shfl_xor_sync(0xffffffffu, mx1, 2));

        float mn0 = fmaxf(m0, mx0), mn1 = fmaxf(m1, mx1);
        float al0 = __expf(m0 - mn0), al1 = __expf(m1 - mn1);
        m0 = mn0; m1 = mn1;

        // ---- exp + row sums ----
        float s0 = 0.0f, s1 = 0.0f;
#pragma unroll
        for (int g = 0; g < 8; g++) {
            float p0 = (sc[g][0] > -1e29f) ? __expf(sc[g][0] - mn0) : 0.0f;
            float p1 = (sc[g][1] > -1e29f) ? __expf(sc[g][1] - mn0) : 0.0f;
            float p2 = (sc[g][2] > -1e29f) ? __expf(sc[g][2] - mn1) : 0.0f;
            float p3 = (sc[g][3] > -1e29f) ? __expf(sc[g][3] - mn1) : 0.0f;
            sc[g][0] = p0; sc[g][1] = p1; sc[g][2] = p2; sc[g][3] = p3;
            s0 += p0 + p1;
            s1 += p2 + p3;
        }
        s0 += __shfl_xor_sync(0xffffffffu, s0, 1);
        s0 += __shfl_xor_sync(0xffffffffu, s0, 2);
        s1 += __shfl_xor_sync(0xffffffffu, s1, 1);
        s1 += __shfl_xor_sync(0xffffffffu, s1, 2);
        l0 = l0 * al0 + s0;
        l1 = l1 * al1 + s1;

        // ---- rescale acc, pack P to fp16 ----
        uint32_t pf[8][2];
#pragma unroll
        for (int g = 0; g < 8; g++) {
            acc[g][0] *= al0; acc[g][1] *= al0;
            acc[g][2] *= al1; acc[g][3] *= al1;
            pf[g][0] = pack_h2(sc[g][0], sc[g][1]);
            pf[g][1] = pack_h2(sc[g][2], sc[g][3]);
        }

        // ---- O += P V ----
#pragma unroll
        for (int jj = 0; jj < 4; jj++) {
            uint32_t a[4] = { pf[2 * jj][0], pf[2 * jj][1],
                              pf[2 * jj + 1][0], pf[2 * jj + 1][1] };
#pragma unroll
            for (int dg = 0; dg < 4; dg++) {
                int r = jj * 16 + vrow;
                uint32_t bd = sv + (uint32_t)r * 128u +
                              (uint32_t)(((dg * 2 + vc8) ^ (r & 7)) << 4);
                uint32_t bf[4];
                ldmx4t(bf, bd);
                mma16816(acc[2 * dg],     a, bf);
                mma16816(acc[2 * dg + 1], a, bf + 2);
            }
        }
        __syncthreads();
    }
#undef PREFETCH

    // ---- epilogue: normalize + store fp16 ----
    const float i0 = 1.0f / l0, i1 = 1.0f / l1;
    const size_t base0 = ((size_t)(b * Sn) + r0g) * (Hn * DHn) + h * 64;
    const size_t base1 = ((size_t)(b * Sn) + r1g) * (Hn * DHn) + h * 64;
#pragma unroll
    for (int g = 0; g < 8; g++) {
        int d = g * 8 + (lane & 3) * 2;
        uint32_t o0 = pack_h2(acc[g][0] * i0, acc[g][1] * i0);
        uint32_t o1 = pack_h2(acc[g][2] * i1, acc[g][3] * i1);
        *(uint32_t*)(att + base0 + d) = o0;
        *(uint32_t*)(att + base1 + d) = o1;
    }
}

// ============================================================
extern "C" void kernel_launch(void* const* d_in, const int* in_sizes, int n_in,
                              void* d_out, int out_size)
{
    const float* x    = (const float*)d_in[0];
    const float* Wq   = (const float*)d_in[1];
    const float* bq   = (const float*)d_in[2];
    const float* Wk   = (const float*)d_in[3];
    const float* bk   = (const float*)d_in[4];
    const float* Wv   = (const float*)d_in[5];
    const float* bv   = (const float*)d_in[6];
    const float* Wo   = (const float*)d_in[7];
    const float* bo   = (const float*)d_in[8];
    const float* qn   = (const float*)d_in[9];
    const float* kn   = (const float*)d_in[10];
    const float* cosT = (const float*)d_in[11];
    const float* sinT = (const float*)d_in[12];
    float* out = (float*)d_out;

    float *gq, *gk, *gv;
    __half *xh, *qh, *kh, *vh, *ah, *wq, *wk, *wv, *wo;
    cudaGetSymbolAddress((void**)&gq, g_q);
    cudaGetSymbolAddress((void**)&gk, g_k);
    cudaGetSymbolAddress((void**)&gv, g_v);
    cudaGetSymbolAddress((void**)&xh, g_xh);
    cudaGetSymbolAddress((void**)&qh, g_qh);
    cudaGetSymbolAddress((void**)&kh, g_kh);
    cudaGetSymbolAddress((void**)&vh, g_vh);
    cudaGetSymbolAddress((void**)&ah, g_ah);
    cudaGetSymbolAddress((void**)&wq, g_wq);
    cudaGetSymbolAddress((void**)&wk, g_wk);
    cudaGetSymbolAddress((void**)&wv, g_wv);
    cudaGetSymbolAddress((void**)&wo, g_wo);

    cudaFuncSetAttribute(mm_hmma_kernel,
                         cudaFuncAttributeMaxDynamicSharedMemorySize, 65536);
    const int DSMEM = 65536;

    // converts
    const int n4x = Mtok * Dn / 4;
    cvt_kernel<<<(n4x + 255) / 256, 256>>>(x, xh, n4x);
    tcvt_kernel<<<dim3(1024 / 32, 1024 / 32), dim3(32, 8)>>>(Wq, wq, 1024, 1024);
    tcvt_kernel<<<dim3(256  / 32, 1024 / 32), dim3(32, 8)>>>(Wk, wk, 1024, 256);
    tcvt_kernel<<<dim3(256  / 32, 1024 / 32), dim3(32, 8)>>>(Wv, wv, 1024, 256);
    tcvt_kernel<<<dim3(1024 / 32, 1024 / 32), dim3(32, 8)>>>(Wo, wo, 1024, 1024);

    // QKV projections
    mm_hmma_kernel<<<dim3(8, 128), 256, DSMEM>>>(xh, wq, bq, gq, 1024, 1024);
    mm_hmma_kernel<<<dim3(2, 128), 256, DSMEM>>>(xh, wk, bk, gk, 256, 1024);
    mm_hmma_kernel<<<dim3(2, 128), 256, DSMEM>>>(xh, wv, bv, gv, 256, 1024);

    // RMSNorm + RoPE -> fp16
    norm_rope_kernel<<<Mtok, 256>>>(gq, gk, gv, qn, kn, cosT, sinT, qh, kh, vh);

    // HMMA flash attention -> fp16
    attn_mma_kernel<<<dim3(Sn / 64, Hn, Bn), 128>>>(qh, kh, vh, ah);

    // Output projection -> d_out (fp32 + bias)
    mm_hmma_kernel<<<dim3(8, 128), 256, DSMEM>>>(ah, wo, bo, out, 1024, 1024);
}

// round 6
// speedup vs baseline: 6.7479x; 1.0764x over previous
#include <cuda_runtime.h>
#include <cuda_fp16.h>
#include <cstdint>

#define Bn   4
#define Sn   4096
#define Dn   1024
#define Hn   16
#define HKVn 4
#define DHn  64
#define Mtok (Bn*Sn)            // 16384

// ---- scratch ----
__device__ __half g_xh [Mtok * Dn];                 // x fp16
__device__ __half g_qh [Bn * Hn   * Sn * DHn];      // normed+roped+prescaled fp16
__device__ __half g_kh [Bn * HKVn * Sn * DHn];
__device__ __half g_vh [Bn * HKVn * Sn * DHn];
__device__ __half g_ah [Mtok * Hn * DHn];           // attention out fp16
__device__ __half g_wqkv[1536 * Dn];                // concat [Nq|Nk|Nv][K] fp16
__device__ __half g_wo  [Hn * DHn * Dn];            // [N,K] fp16

// ============================================================
// helpers
// ============================================================
__device__ __forceinline__ uint32_t smem_u32(const void* p) {
    uint32_t a;
    asm("{ .reg .u64 t; cvta.to.shared.u64 t, %1; cvt.u32.u64 %0, t; }" : "=r"(a) : "l"(p));
    return a;
}
__device__ __forceinline__ void cp16(uint32_t dst, const void* src) {
    asm volatile("cp.async.cg.shared.global [%0], [%1], 16;" :: "r"(dst), "l"(src));
}
#define CP_COMMIT() asm volatile("cp.async.commit_group;" ::: "memory")
#define CP_WAIT0()  asm volatile("cp.async.wait_group 0;" ::: "memory")
#define CP_WAIT1()  asm volatile("cp.async.wait_group 1;" ::: "memory")
#define CP_WAIT3()  asm volatile("cp.async.wait_group 3;" ::: "memory")

__device__ __forceinline__ void ldmx4(uint32_t* r, uint32_t addr) {
    asm volatile("ldmatrix.sync.aligned.m8n8.x4.shared.b16 {%0,%1,%2,%3}, [%4];"
        : "=r"(r[0]), "=r"(r[1]), "=r"(r[2]), "=r"(r[3]) : "r"(addr));
}
__device__ __forceinline__ void ldmx4t(uint32_t* r, uint32_t addr) {
    asm volatile("ldmatrix.sync.aligned.m8n8.x4.trans.shared.b16 {%0,%1,%2,%3}, [%4];"
        : "=r"(r[0]), "=r"(r[1]), "=r"(r[2]), "=r"(r[3]) : "r"(addr));
}
__device__ __forceinline__ void mma16816(float* c, const uint32_t* a, const uint32_t* b) {
    asm volatile("mma.sync.aligned.m16n8k16.row.col.f32.f16.f16.f32 "
        "{%0,%1,%2,%3}, {%4,%5,%6,%7}, {%8,%9}, {%0,%1,%2,%3};"
        : "+f"(c[0]), "+f"(c[1]), "+f"(c[2]), "+f"(c[3])
        : "r"(a[0]), "r"(a[1]), "r"(a[2]), "r"(a[3]), "r"(b[0]), "r"(b[1]));
}
__device__ __forceinline__ uint32_t pack_h2(float a, float b) {
    __half2 h = __floats2half2_rn(a, b);
    return *reinterpret_cast<uint32_t*>(&h);
}

// ============================================================
// convert fp32 -> fp16 (float4 vectorized)
// ============================================================
__global__ __launch_bounds__(256) void cvt_kernel(
    const float* __restrict__ s, __half* __restrict__ d, int n4)
{
    int i = blockIdx.x * 256 + threadIdx.x;
    if (i >= n4) return;
    float4 v = ((const float4*)s)[i];
    ushort4 o;
    o.x = __half_as_ushort(__float2half_rn(v.x));
    o.y = __half_as_ushort(__float2half_rn(v.y));
    o.z = __half_as_ushort(__float2half_rn(v.z));
    o.w = __half_as_ushort(__float2half_rn(v.w));
    ((ushort4*)d)[i] = o;
}

// ============================================================
// transpose + convert: W[K,N] fp32 -> [N,K] fp16
// ============================================================
__global__ __launch_bounds__(256) void tcvt_kernel(
    const float* __restrict__ W, __half* __restrict__ o, int K, int N)
{
    __shared__ float tile[32][33];
    int n0 = blockIdx.x * 32, k0 = blockIdx.y * 32;
    int tx = threadIdx.x, ty = threadIdx.y;      // 32 x 8
    for (int r = ty; r < 32; r += 8)
        tile[r][tx] = W[(size_t)(k0 + r) * N + n0 + tx];
    __syncthreads();
    for (int r = ty; r < 32; r += 8)
        o[(size_t)(n0 + r) * K + k0 + tx] = __float2half_rn(tile[tx][r]);
}

// ============================================================
// shared GEMM mainloop (128x128 tile, BK=32, 4-stage cp.async, 8 warps)
// computes acc[2][8][4] per warp; A[M,K], B[N,K] fp16 row-major-K.
// ============================================================
#define GEMM_MAINLOOP(gA, gB, K) do { \
    const int lr = t >> 2; \
    const int lc16 = t & 3; \
    const int NCH = (K) >> 5; \
    _Pragma("unroll") \
    for (int s = 0; s < 4; s++) { \
        uint32_t sb_ = sbase + (uint32_t)s * 16384u; \
        _Pragma("unroll") \
        for (int i_ = 0; i_ < 2; i_++) { \
            int row_ = i_ * 64 + lr; \
            uint32_t sw_ = (uint32_t)row_ * 64u + (uint32_t)((lc16 ^ ((row_ >> 1) & 3)) << 4); \
            size_t go_ = (size_t)row_ * (K) + (size_t)s * 32 + lc16 * 8; \
            cp16(sb_ + sw_,         (gA) + go_); \
            cp16(sb_ + 8192u + sw_, (gB) + go_); \
        } \
        CP_COMMIT(); \
    } \
    for (int c = 0; c < NCH; c++) { \
        CP_WAIT3(); \
        __syncthreads(); \
        const uint32_t sb = sbase + (uint32_t)(c & 3) * 16384u; \
        _Pragma("unroll") \
        for (int ks = 0; ks < 2; ks++) { \
            uint32_t ahf[2][4], bhf[4][4]; \
            _Pragma("unroll") \
            for (int mt = 0; mt < 2; mt++) { \
                int r = a_row + mt * 16; \
                uint32_t ad = sb + (uint32_t)r * 64u + \
                              (uint32_t)(((ks * 2 + a_k8) ^ ((r >> 1) & 3)) << 4); \
                ldmx4(ahf[mt], ad); \
            } \
            _Pragma("unroll") \
            for (int g = 0; g < 4; g++) { \
                int r = b_row + g * 16; \
                uint32_t bd = sb + 8192u + (uint32_t)r * 64u + \
                              (uint32_t)(((ks * 2 + b_k8) ^ ((r >> 1) & 3)) << 4); \
                ldmx4(bhf[g], bd); \
            } \
            _Pragma("unroll") \
            for (int mt = 0; mt < 2; mt++) \
                _Pragma("unroll") \
                for (int j = 0; j < 8; j++) \
                    mma16816(acc[mt][j], ahf[mt], &bhf[j >> 1][(j & 1) * 2]); \
        } \
        __syncthreads(); \
        if (c + 4 < NCH) { \
            uint32_t sb_ = sbase + (uint32_t)(c & 3) * 16384u; \
            _Pragma("unroll") \
            for (int i_ = 0; i_ < 2; i_++) { \
                int row_ = i_ * 64 + lr; \
                uint32_t sw_ = (uint32_t)row_ * 64u + (uint32_t)((lc16 ^ ((row_ >> 1) & 3)) << 4); \
                size_t go_ = (size_t)row_ * (K) + (size_t)(c + 4) * 32 + lc16 * 8; \
                cp16(sb_ + sw_,         (gA) + go_); \
                cp16(sb_ + 8192u + sw_, (gB) + go_); \
            } \
        } \
        CP_COMMIT(); \
    } } while (0)

// ============================================================
// Fused QKV GEMM + bias + RMSNorm + RoPE + fp16 transpose store.
// N = 1536 (Q:0-1023, K:1024-1279, V:1280-1535), K = 1024.
// Each warp's 64-col slice == one head. Q pre-scaled by 1/8.
// ============================================================
__global__ __launch_bounds__(256, 2) void mm_qkv_fused_kernel(
    const __half* __restrict__ Ah, const __half* __restrict__ Bw,
    const float* __restrict__ bq, const float* __restrict__ bk,
    const float* __restrict__ bv,
    const float* __restrict__ qnw, const float* __restrict__ knw,
    const float* __restrict__ cosT, const float* __restrict__ sinT,
    __half* __restrict__ qh, __half* __restrict__ kh, __half* __restrict__ vh)
{
    extern __shared__ char sm[];
    const int t = threadIdx.x, wid = t >> 5, lane = t & 31;
    const int m0 = blockIdx.y * 128, n0 = blockIdx.x * 128;
    const uint32_t sbase = smem_u32(sm);
    const int K = Dn;

    const __half* gA = Ah + (size_t)m0 * K;
    const __half* gB = Bw + (size_t)n0 * K;

    const int warp_m = wid & 3;
    const int warp_n = wid >> 2;
    const int a_row = warp_m * 32 + (lane & 15);
    const int a_k8  = lane >> 4;
    const int b_row = warp_n * 64 + (lane & 7) + ((lane >> 4) << 3);
    const int b_k8  = (lane >> 3) & 1;

    float acc[2][8][4];
#pragma unroll
    for (int a = 0; a < 2; a++)
#pragma unroll
        for (int b = 0; b < 8; b++)
#pragma unroll
            for (int cq = 0; cq < 4; cq++) acc[a][b][cq] = 0.0f;

    GEMM_MAINLOOP(gA, gB, K);

    // ---- fused epilogue ----
    const int gc = n0 + warp_n * 64;         // head-aligned 64-col slice
    const int q2 = (lane & 3) * 2;

    int mode, hh, NHd;
    __half* dst;
    const float* bptr;
    const float* wn = qnw;
    if (gc < 1024)      { mode = 0; hh = gc >> 6;          dst = qh; bptr = bq + gc;          wn = qnw; NHd = Hn;  }
    else if (gc < 1280) { mode = 1; hh = (gc - 1024) >> 6; dst = kh; bptr = bk + (gc - 1024); wn = knw; NHd = HKVn; }
    else                { mode = 2; hh = (gc - 1280) >> 6; dst = vh; bptr = bv + (gc - 1280); NHd = HKVn; }

    float bvv[8][2], wnv[8][2];
#pragma unroll
    for (int j = 0; j < 8; j++) {
        bvv[j][0] = bptr[j * 8 + q2];
        bvv[j][1] = bptr[j * 8 + q2 + 1];
    }
    if (mode < 2) {
#pragma unroll
        for (int j = 0; j < 8; j++) {
            wnv[j][0] = wn[j * 8 + q2];
            wnv[j][1] = wn[j * 8 + q2 + 1];
        }
    }

#pragma unroll
    for (int mt = 0; mt < 2; mt++) {
#pragma unroll
        for (int pr = 0; pr < 2; pr++) {
            const int row = m0 + warp_m * 32 + (lane >> 2) + mt * 16 + pr * 8;
            const int s  = row & (Sn - 1);
            const int bb = row >> 12;
            float v[8][2];
#pragma unroll
            for (int j = 0; j < 8; j++) {
                v[j][0] = acc[mt][j][pr * 2]     + bvv[j][0];
                v[j][1] = acc[mt][j][pr * 2 + 1] + bvv[j][1];
            }
            if (mode < 2) {
                float ss = 0.0f;
#pragma unroll
                for (int j = 0; j < 8; j++) ss += v[j][0] * v[j][0] + v[j][1] * v[j][1];
                ss += __shfl_xor_sync(0xffffffffu, ss, 1);
                ss += __shfl_xor_sync(0xffffffffu, ss, 2);
                float r = rsqrtf(ss * (1.0f / 64.0f) + 1e-6f);
#pragma unroll
                for (int j = 0; j < 8; j++) {
                    v[j][0] *= r * wnv[j][0];
                    v[j][1] *= r * wnv[j][1];
                }
                // RoPE: pair (d, d+32) = (j, j+4) same lane
                const float* cr = cosT + s * 64;
                const float* sr = sinT + s * 64;
#pragma unroll
                for (int j = 0; j < 4; j++) {
#pragma unroll
                    for (int p = 0; p < 2; p++) {
                        int d = j * 8 + q2 + p;
                        float x0 = v[j][p], x1 = v[j + 4][p];
                        v[j][p]     = x0 * cr[d]      - x1 * sr[d];
                        v[j + 4][p] = x1 * cr[d + 32] + x0 * sr[d + 32];
                    }
                }
                if (mode == 0) {
#pragma unroll
                    for (int j = 0; j < 8; j++) { v[j][0] *= 0.125f; v[j][1] *= 0.125f; }
                }
            }
            __half* dp = dst + (((size_t)(bb * NHd + hh)) * Sn + s) * 64;
#pragma unroll
            for (int j = 0; j < 8; j++)
                *(uint32_t*)(dp + j * 8 + q2) = pack_h2(v[j][0], v[j][1]);
        }
    }
}

// ============================================================
// Standard HMMA GEMM (for O-projection): fp32 out + bias
// ============================================================
__global__ __launch_bounds__(256, 2) void mm_hmma_kernel(
    const __half* __restrict__ Ah, const __half* __restrict__ Bh,
    const float* __restrict__ bias, float* __restrict__ Cm, int N, int K)
{
    extern __shared__ char sm[];
    const int t = threadIdx.x, wid = t >> 5, lane = t & 31;
    const int m0 = blockIdx.y * 128, n0 = blockIdx.x * 128;
    const uint32_t sbase = smem_u32(sm);

    const __half* gA = Ah + (size_t)m0 * K;
    const __half* gB = Bh + (size_t)n0 * K;

    const int warp_m = wid & 3;
    const int warp_n = wid >> 2;
    const int a_row = warp_m * 32 + (lane & 15);
    const int a_k8  = lane >> 4;
    const int b_row = warp_n * 64 + (lane & 7) + ((lane >> 4) << 3);
    const int b_k8  = (lane >> 3) & 1;

    float acc[2][8][4];
#pragma unroll
    for (int a = 0; a < 2; a++)
#pragma unroll
        for (int b = 0; b < 8; b++)
#pragma unroll
            for (int cq = 0; cq < 4; cq++) acc[a][b][cq] = 0.0f;

    GEMM_MAINLOOP(gA, gB, K);

    const int crow = m0 + warp_m * 32 + (lane >> 2);
    const int ccol = n0 + warp_n * 64 + (lane & 3) * 2;
#pragma unroll
    for (int j = 0; j < 8; j++) {
        int col = ccol + j * 8;
        float b0 = bias[col], b1 = bias[col + 1];
#pragma unroll
        for (int mt = 0; mt < 2; mt++) {
            int r0 = crow + mt * 16;
            float2 o0 = make_float2(acc[mt][j][0] + b0, acc[mt][j][1] + b1);
            float2 o1 = make_float2(acc[mt][j][2] + b0, acc[mt][j][3] + b1);
            *(float2*)(Cm + (size_t)r0 * N + col)       = o0;
            *(float2*)(Cm + (size_t)(r0 + 8) * N + col) = o1;
        }
    }
}

// ============================================================
// HMMA sliding-window flash attention (Q pre-scaled by 1/8).
// Masking only needed for tiles at window offsets -128 / +128.
// ============================================================
__global__ __launch_bounds__(128) void attn_mma_kernel(
    const __half* __restrict__ qh, const __half* __restrict__ kh,
    const __half* __restrict__ vh, __half* __restrict__ att)
{
    __shared__ __half Qs[64 * 64];
    __shared__ __half Ks[2][64 * 64];
    __shared__ __half Vs[2][64 * 64];

    const int t = threadIdx.x, wm = t >> 5, lane = t & 31;
    const int q0 = blockIdx.x * 64;
    const int h  = blockIdx.y;
    const int b  = blockIdx.z;
    const int hk = h >> 2;

    const __half* Qg = qh + (((size_t)(b * Hn + h) * Sn) + q0) * 64;
    const __half* Kg = kh + ((size_t)(b * HKVn + hk) * Sn) * 64;
    const __half* Vg = vh + ((size_t)(b * HKVn + hk) * Sn) * 64;

    const uint32_t sQ = smem_u32(Qs);
    const uint32_t sK = smem_u32(Ks);
    const uint32_t sV = smem_u32(Vs);

    for (int i = t; i < 512; i += 128) {
        int row = i >> 3, c = i & 7;
        uint32_t sw = (uint32_t)row * 128u + (uint32_t)((c ^ (row & 7)) << 4);
        cp16(sQ + sw, Qg + row * 64 + c * 8);
    }

    int lo = 0; while (q0 - 128 + lo * 64 < 0) lo++;
    int hi = 4; while (q0 - 128 + hi * 64 + 64 > Sn) hi--;

#define PREFETCH(it, buf) do { \
    int kb_ = q0 - 128 + (it) * 64; \
    const __half* Kt_ = Kg + (size_t)kb_ * 64; \
    const __half* Vt_ = Vg + (size_t)kb_ * 64; \
    uint32_t sk_ = sK + (uint32_t)(buf) * 8192u; \
    uint32_t sv_ = sV + (uint32_t)(buf) * 8192u; \
    for (int i_ = t; i_ < 512; i_ += 128) { \
        int row_ = i_ >> 3, c_ = i_ & 7; \
        uint32_t sw_ = (uint32_t)row_ * 128u + (uint32_t)((c_ ^ (row_ & 7)) << 4); \
        cp16(sk_ + sw_, Kt_ + row_ * 64 + c_ * 8); \
        cp16(sv_ + sw_, Vt_ + row_ * 64 + c_ * 8); \
    } } while (0)

    PREFETCH(lo, 0);
    CP_COMMIT();

    const int arow = wm * 16 + (lane & 15);
    const int ak8  = lane >> 4;
    const int brow = (lane & 7) + ((lane >> 4) << 3);
    const int bk8  = (lane >> 3) & 1;
    const int vrow = (lane & 7) + (((lane >> 3) & 1) << 3);
    const int vc8  = lane >> 4;

    const int r0g = q0 + wm * 16 + (lane >> 2);
    const int r1g = r0g + 8;

    float acc[8][4];
#pragma unroll
    for (int g = 0; g < 8; g++)
#pragma unroll
        for (int e = 0; e < 4; e++) acc[g][e] = 0.0f;
    float m0 = -1e30f, m1 = -1e30f, l0 = 0.0f, l1 = 0.0f;

    uint32_t qf[4][4];
    bool qloaded = false;

    for (int it = lo; it <= hi; ++it) {
        const int buf = (it - lo) & 1;
        if (it < hi) { PREFETCH(it + 1, buf ^ 1); CP_COMMIT(); CP_WAIT1(); }
        else { CP_WAIT0(); }
        __syncthreads();

        if (!qloaded) {
#pragma unroll
            for (int kblk = 0; kblk < 4; kblk++) {
                uint32_t ad = sQ + (uint32_t)arow * 128u +
                              (uint32_t)(((kblk * 2 + ak8) ^ (arow & 7)) << 4);
                ldmx4(qf[kblk], ad);
            }
            qloaded = true;
        }

        const int kb = q0 - 128 + it * 64;
        const uint32_t sk = sK + (uint32_t)buf * 8192u;
        const uint32_t sv = sV + (uint32_t)buf * 8192u;
        const bool need_mask = (it == 0) || (it == 4);

        float sc[8][4];
#pragma unroll
        for (int g = 0; g < 8; g++)
#pragma unroll
            for (int e = 0; e < 4; e++) sc[g][e] = 0.0f;
#pragma unroll
        for (int kblk = 0; kblk < 4; kblk++) {
#pragma unroll
            for (int g = 0; g < 4; g++) {
                int r = g * 16 + brow;
                uint32_t bd = sk + (uint32_t)r * 128u +
                              (uint32_t)(((kblk * 2 + bk8) ^ (r & 7)) << 4);
                uint32_t bf[4];
                ldmx4(bf, bd);
                mma16816(sc[2 * g],     qf[kblk], bf);
                mma16816(sc[2 * g + 1], qf[kblk], bf + 2);
            }
        }

        if (need_mask) {
#pragma unroll
            for (int g = 0; g < 8; g++) {
                int j0 = kb + g * 8 + (lane & 3) * 2;
                int j1 = j0 + 1;
                if (abs(j0 - r0g) > 128) sc[g][0] = -1e30f;
                if (abs(j1 - r0g) > 128) sc[g][1] = -1e30f;
                if (abs(j0 - r1g) > 128) sc[g][2] = -1e30f;
                if (abs(j1 - r1g) > 128) sc[g][3] = -1e30f;
            }
        }

        float mx0 = -1e30f, mx1 = -1e30f;
#pragma unroll
        for (int g = 0; g < 8; g++) {
            mx0 = fmaxf(mx0, fmaxf(sc[g][0], sc[g][1]));
            mx1 = fmaxf(mx1, fmaxf(sc[g][2], sc[g][3]));
        }
        mx0 = fmaxf(mx0, __shfl_xor_sync(0xffffffffu, mx0, 1));
        mx0 = fmaxf(mx0, __shfl_xor_sync(0xffffffffu, mx0, 2));
        mx1 = fmaxf(mx1, __shfl_xor_sync(0xffffffffu, mx1, 1));
        mx1 = fmaxf(mx1, __shfl_xor_sync(0xffffffffu, mx1, 2));

        float mn0 = fmaxf(m0, mx0), mn1 = fmaxf(m1, mx1);
        float al0 = __expf(m0 - mn0), al1 = __expf(m1 - mn1);
        m0 = mn0; m1 = mn1;

        float s0 = 0.0f, s1 = 0.0f;
        if (need_mask) {
#pragma unroll
            for (int g = 0; g < 8; g++) {
                float p0 = (sc[g][0] > -1e29f) ? __expf(sc[g][0] - mn0) : 0.0f;
                float p1 = (sc[g][1] > -1e29f) ? __expf(sc[g][1] - mn0) : 0.0f;
                float p2 = (sc[g][2] > -1e29f) ? __expf(sc[g][2] - mn1) : 0.0f;
                float p3 = (sc[g][3] > -1e29f) ? __expf(sc[g][3] - mn1) : 0.0f;
                sc[g][0] = p0; sc[g][1] = p1; sc[g][2] = p2; sc[g][3] = p3;
                s0 += p0 + p1;
                s1 += p2 + p3;
            }
        } else {
#pragma unroll
            for (int g = 0; g < 8; g++) {
                float p0 = __expf(sc[g][0] - mn0);
                float p1 = __expf(sc[g][1] - mn0);
                float p2 = __expf(sc[g][2] - mn1);
                float p3 = __expf(sc[g][3] - mn1);
                sc[g][0] = p0; sc[g][1] = p1; sc[g][2] = p2; sc[g][3] = p3;
                s0 += p0 + p1;
                s1 += p2 + p3;
            }
        }
        s0 += __shfl_xor_sync(0xffffffffu, s0, 1);
        s0 += __shfl_xor_sync(0xffffffffu, s0, 2);
        s1 += __shfl_xor_sync(0xffffffffu, s1, 1);
        s1 += __shfl_xor_sync(0xffffffffu, s1, 2);
        l0 = l0 * al0 + s0;
        l1 = l1 * al1 + s1;

        uint32_t pf[8][2];
#pragma unroll
        for (int g = 0; g < 8; g++) {
            acc[g][0] *= al0; acc[g][1] *= al0;
            acc[g][2] *= al1; acc[g][3] *= al1;
            pf[g][0] = pack_h2(sc[g][0], sc[g][1]);
            pf[g][1] = pack_h2(sc[g][2], sc[g][3]);
        }

#pragma unroll
        for (int jj = 0; jj < 4; jj++) {
            uint32_t a[4] = { pf[2 * jj][0], pf[2 * jj][1],
                              pf[2 * jj + 1][0], pf[2 * jj + 1][1] };
#pragma unroll
            for (int dg = 0; dg < 4; dg++) {
                int r = jj * 16 + vrow;
                uint32_t bd = sv + (uint32_t)r * 128u +
                              (uint32_t)(((dg * 2 + vc8) ^ (r & 7)) << 4);
                uint32_t bf[4];
                ldmx4t(bf, bd);
                mma16816(acc[2 * dg],     a, bf);
                mma16816(acc[2 * dg + 1], a, bf + 2);
            }
        }
        __syncthreads();
    }
#undef PREFETCH

    const float i0 = 1.0f / l0, i1 = 1.0f / l1;
    const size_t base0 = ((size_t)(b * Sn) + r0g) * (Hn * DHn) + h * 64;
    const size_t base1 = ((size_t)(b * Sn) + r1g) * (Hn * DHn) + h * 64;
#pragma unroll
    for (int g = 0; g < 8; g++) {
        int d = g * 8 + (lane & 3) * 2;
        *(uint32_t*)(att + base0 + d) = pack_h2(acc[g][0] * i0, acc[g][1] * i0);
        *(uint32_t*)(att + base1 + d) = pack_h2(acc[g][2] * i1, acc[g][3] * i1);
    }
}

// ============================================================
extern "C" void kernel_launch(void* const* d_in, const int* in_sizes, int n_in,
                              void* d_out, int out_size)
{
    const float* x    = (const float*)d_in[0];
    const float* Wq   = (const float*)d_in[1];
    const float* bq   = (const float*)d_in[2];
    const float* Wk   = (const float*)d_in[3];
    const float* bk   = (const float*)d_in[4];
    const float* Wv   = (const float*)d_in[5];
    const float* bv   = (const float*)d_in[6];
    const float* Wo   = (const float*)d_in[7];
    const float* bo   = (const float*)d_in[8];
    const float* qn   = (const float*)d_in[9];
    const float* kn   = (const float*)d_in[10];
    const float* cosT = (const float*)d_in[11];
    const float* sinT = (const float*)d_in[12];
    float* out = (float*)d_out;

    __half *xh, *qh, *kh, *vh, *ah, *wqkv, *wo;
    cudaGetSymbolAddress((void**)&xh,   g_xh);
    cudaGetSymbolAddress((void**)&qh,   g_qh);
    cudaGetSymbolAddress((void**)&kh,   g_kh);
    cudaGetSymbolAddress((void**)&vh,   g_vh);
    cudaGetSymbolAddress((void**)&ah,   g_ah);
    cudaGetSymbolAddress((void**)&wqkv, g_wqkv);
    cudaGetSymbolAddress((void**)&wo,   g_wo);

    cudaFuncSetAttribute(mm_qkv_fused_kernel,
                         cudaFuncAttributeMaxDynamicSharedMemorySize, 65536);
    cudaFuncSetAttribute(mm_hmma_kernel,
                         cudaFuncAttributeMaxDynamicSharedMemorySize, 65536);
    const int DSMEM = 65536;

    // converts (weights into concat buffer: Q rows 0-1023, K 1024-1279, V 1280-1535)
    const int n4x = Mtok * Dn / 4;
    cvt_kernel<<<(n4x + 255) / 256, 256>>>(x, xh, n4x);
    tcvt_kernel<<<dim3(1024 / 32, 1024 / 32), dim3(32, 8)>>>(Wq, wqkv, 1024, 1024);
    tcvt_kernel<<<dim3(256  / 32, 1024 / 32), dim3(32, 8)>>>(Wk, wqkv + 1024 * 1024, 1024, 256);
    tcvt_kernel<<<dim3(256  / 32, 1024 / 32), dim3(32, 8)>>>(Wv, wqkv + 1280 * 1024, 1024, 256);
    tcvt_kernel<<<dim3(1024 / 32, 1024 / 32), dim3(32, 8)>>>(Wo, wo, 1024, 1024);

    // fused QKV projection + norm + rope -> fp16 transposed
    mm_qkv_fused_kernel<<<dim3(12, 128), 256, DSMEM>>>(
        xh, wqkv, bq, bk, bv, qn, kn, cosT, sinT, qh, kh, vh);

    // HMMA flash attention -> fp16
    attn_mma_kernel<<<dim3(Sn / 64, Hn, Bn), 128>>>(qh, kh, vh, ah);

    // Output projection -> d_out (fp32 + bias)
    mm_hmma_kernel<<<dim3(8, 128), 256, DSMEM>>>(ah, wo, bo, out, 1024, 1024);
}

// round 7
// speedup vs baseline: 6.9345x; 1.0277x over previous
#include <cuda_runtime.h>
#include <cuda_fp16.h>
#include <cstdint>

#define Bn   4
#define Sn   4096
#define Dn   1024
#define Hn   16
#define HKVn 4
#define DHn  64
#define Mtok (Bn*Sn)            // 16384

// ---- scratch ----
__device__ __half g_xh [Mtok * Dn];                 // x fp16
__device__ __half g_qh [Bn * Hn   * Sn * DHn];      // normed+roped+prescaled fp16
__device__ __half g_kh [Bn * HKVn * Sn * DHn];
__device__ __half g_vh [Bn * HKVn * Sn * DHn];
__device__ __half g_ah [Mtok * Hn * DHn];           // attention out fp16
__device__ __half g_wqkv[1536 * Dn];                // concat [Nq|Nk|Nv][K] fp16
__device__ __half g_wo  [Hn * DHn * Dn];            // [N,K] fp16

// ============================================================
// helpers
// ============================================================
__device__ __forceinline__ uint32_t smem_u32(const void* p) {
    uint32_t a;
    asm("{ .reg .u64 t; cvta.to.shared.u64 t, %1; cvt.u32.u64 %0, t; }" : "=r"(a) : "l"(p));
    return a;
}
__device__ __forceinline__ void cp16(uint32_t dst, const void* src) {
    asm volatile("cp.async.cg.shared.global [%0], [%1], 16;" :: "r"(dst), "l"(src));
}
#define CP_COMMIT() asm volatile("cp.async.commit_group;" ::: "memory")
#define CP_WAIT0()  asm volatile("cp.async.wait_group 0;" ::: "memory")
#define CP_WAIT1()  asm volatile("cp.async.wait_group 1;" ::: "memory")
#define CP_WAIT3()  asm volatile("cp.async.wait_group 3;" ::: "memory")

__device__ __forceinline__ void ldmx4(uint32_t* r, uint32_t addr) {
    asm volatile("ldmatrix.sync.aligned.m8n8.x4.shared.b16 {%0,%1,%2,%3}, [%4];"
        : "=r"(r[0]), "=r"(r[1]), "=r"(r[2]), "=r"(r[3]) : "r"(addr));
}
__device__ __forceinline__ void ldmx4t(uint32_t* r, uint32_t addr) {
    asm volatile("ldmatrix.sync.aligned.m8n8.x4.trans.shared.b16 {%0,%1,%2,%3}, [%4];"
        : "=r"(r[0]), "=r"(r[1]), "=r"(r[2]), "=r"(r[3]) : "r"(addr));
}
__device__ __forceinline__ void mma16816(float* c, const uint32_t* a, const uint32_t* b) {
    asm volatile("mma.sync.aligned.m16n8k16.row.col.f32.f16.f16.f32 "
        "{%0,%1,%2,%3}, {%4,%5,%6,%7}, {%8,%9}, {%0,%1,%2,%3};"
        : "+f"(c[0]), "+f"(c[1]), "+f"(c[2]), "+f"(c[3])
        : "r"(a[0]), "r"(a[1]), "r"(a[2]), "r"(a[3]), "r"(b[0]), "r"(b[1]));
}
__device__ __forceinline__ uint32_t pack_h2(float a, float b) {
    __half2 h = __floats2half2_rn(a, b);
    return *reinterpret_cast<uint32_t*>(&h);
}

// ============================================================
// convert fp32 -> fp16
// ============================================================
__global__ __launch_bounds__(256) void cvt_kernel(
    const float* __restrict__ s, __half* __restrict__ d, int n4)
{
    int i = blockIdx.x * 256 + threadIdx.x;
    if (i >= n4) return;
    float4 v = ((const float4*)s)[i];
    ushort4 o;
    o.x = __half_as_ushort(__float2half_rn(v.x));
    o.y = __half_as_ushort(__float2half_rn(v.y));
    o.z = __half_as_ushort(__float2half_rn(v.z));
    o.w = __half_as_ushort(__float2half_rn(v.w));
    ((ushort4*)d)[i] = o;
}

// ============================================================
// transpose + convert: W[K,N] fp32 -> [N,K] fp16
// ============================================================
__global__ __launch_bounds__(256) void tcvt_kernel(
    const float* __restrict__ W, __half* __restrict__ o, int K, int N)
{
    __shared__ float tile[32][33];
    int n0 = blockIdx.x * 32, k0 = blockIdx.y * 32;
    int tx = threadIdx.x, ty = threadIdx.y;      // 32 x 8
    for (int r = ty; r < 32; r += 8)
        tile[r][tx] = W[(size_t)(k0 + r) * N + n0 + tx];
    __syncthreads();
    for (int r = ty; r < 32; r += 8)
        o[(size_t)(n0 + r) * K + k0 + tx] = __float2half_rn(tile[tx][r]);
}

// ============================================================
// shared GEMM mainloop (128x128 tile, BK=32, 4-stage cp.async, 8 warps)
// ============================================================
#define GEMM_MAINLOOP(gA, gB, K) do { \
    const int lr = t >> 2; \
    const int lc16 = t & 3; \
    const int NCH = (K) >> 5; \
    _Pragma("unroll") \
    for (int s = 0; s < 4; s++) { \
        uint32_t sb_ = sbase + (uint32_t)s * 16384u; \
        _Pragma("unroll") \
        for (int i_ = 0; i_ < 2; i_++) { \
            int row_ = i_ * 64 + lr; \
            uint32_t sw_ = (uint32_t)row_ * 64u + (uint32_t)((lc16 ^ ((row_ >> 1) & 3)) << 4); \
            size_t go_ = (size_t)row_ * (K) + (size_t)s * 32 + lc16 * 8; \
            cp16(sb_ + sw_,         (gA) + go_); \
            cp16(sb_ + 8192u + sw_, (gB) + go_); \
        } \
        CP_COMMIT(); \
    } \
    for (int c = 0; c < NCH; c++) { \
        CP_WAIT3(); \
        __syncthreads(); \
        const uint32_t sb = sbase + (uint32_t)(c & 3) * 16384u; \
        _Pragma("unroll") \
        for (int ks = 0; ks < 2; ks++) { \
            uint32_t ahf[2][4], bhf[4][4]; \
            _Pragma("unroll") \
            for (int mt = 0; mt < 2; mt++) { \
                int r = a_row + mt * 16; \
                uint32_t ad = sb + (uint32_t)r * 64u + \
                              (uint32_t)(((ks * 2 + a_k8) ^ ((r >> 1) & 3)) << 4); \
                ldmx4(ahf[mt], ad); \
            } \
            _Pragma("unroll") \
            for (int g = 0; g < 4; g++) { \
                int r = b_row + g * 16; \
                uint32_t bd = sb + 8192u + (uint32_t)r * 64u + \
                              (uint32_t)(((ks * 2 + b_k8) ^ ((r >> 1) & 3)) << 4); \
                ldmx4(bhf[g], bd); \
            } \
            _Pragma("unroll") \
            for (int mt = 0; mt < 2; mt++) \
                _Pragma("unroll") \
                for (int j = 0; j < 8; j++) \
                    mma16816(acc[mt][j], ahf[mt], &bhf[j >> 1][(j & 1) * 2]); \
        } \
        __syncthreads(); \
        if (c + 4 < NCH) { \
            uint32_t sb_ = sbase + (uint32_t)(c & 3) * 16384u; \
            _Pragma("unroll") \
            for (int i_ = 0; i_ < 2; i_++) { \
                int row_ = i_ * 64 + lr; \
                uint32_t sw_ = (uint32_t)row_ * 64u + (uint32_t)((lc16 ^ ((row_ >> 1) & 3)) << 4); \
                size_t go_ = (size_t)row_ * (K) + (size_t)(c + 4) * 32 + lc16 * 8; \
                cp16(sb_ + sw_,         (gA) + go_); \
                cp16(sb_ + 8192u + sw_, (gB) + go_); \
            } \
        } \
        CP_COMMIT(); \
    } } while (0)

// ============================================================
// Fused QKV GEMM + bias + RMSNorm + RoPE + fp16 transpose store.
// ============================================================
__global__ __launch_bounds__(256, 2) void mm_qkv_fused_kernel(
    const __half* __restrict__ Ah, const __half* __restrict__ Bw,
    const float* __restrict__ bq, const float* __restrict__ bk,
    const float* __restrict__ bv,
    const float* __restrict__ qnw, const float* __restrict__ knw,
    const float* __restrict__ cosT, const float* __restrict__ sinT,
    __half* __restrict__ qh, __half* __restrict__ kh, __half* __restrict__ vh)
{
    extern __shared__ char sm[];
    const int t = threadIdx.x, wid = t >> 5, lane = t & 31;
    const int m0 = blockIdx.y * 128, n0 = blockIdx.x * 128;
    const uint32_t sbase = smem_u32(sm);
    const int K = Dn;

    const __half* gA = Ah + (size_t)m0 * K;
    const __half* gB = Bw + (size_t)n0 * K;

    const int warp_m = wid & 3;
    const int warp_n = wid >> 2;
    const int a_row = warp_m * 32 + (lane & 15);
    const int a_k8  = lane >> 4;
    const int b_row = warp_n * 64 + (lane & 7) + ((lane >> 4) << 3);
    const int b_k8  = (lane >> 3) & 1;

    float acc[2][8][4];
#pragma unroll
    for (int a = 0; a < 2; a++)
#pragma unroll
        for (int b = 0; b < 8; b++)
#pragma unroll
            for (int cq = 0; cq < 4; cq++) acc[a][b][cq] = 0.0f;

    GEMM_MAINLOOP(gA, gB, K);

    const int gc = n0 + warp_n * 64;
    const int q2 = (lane & 3) * 2;

    int mode, hh, NHd;
    __half* dst;
    const float* bptr;
    const float* wn = qnw;
    if (gc < 1024)      { mode = 0; hh = gc >> 6;          dst = qh; bptr = bq + gc;          wn = qnw; NHd = Hn;  }
    else if (gc < 1280) { mode = 1; hh = (gc - 1024) >> 6; dst = kh; bptr = bk + (gc - 1024); wn = knw; NHd = HKVn; }
    else                { mode = 2; hh = (gc - 1280) >> 6; dst = vh; bptr = bv + (gc - 1280); NHd = HKVn; }

    float bvv[8][2], wnv[8][2];
#pragma unroll
    for (int j = 0; j < 8; j++) {
        bvv[j][0] = bptr[j * 8 + q2];
        bvv[j][1] = bptr[j * 8 + q2 + 1];
    }
    if (mode < 2) {
#pragma unroll
        for (int j = 0; j < 8; j++) {
            wnv[j][0] = wn[j * 8 + q2];
            wnv[j][1] = wn[j * 8 + q2 + 1];
        }
    }

#pragma unroll
    for (int mt = 0; mt < 2; mt++) {
#pragma unroll
        for (int pr = 0; pr < 2; pr++) {
            const int row = m0 + warp_m * 32 + (lane >> 2) + mt * 16 + pr * 8;
            const int s  = row & (Sn - 1);
            const int bb = row >> 12;
            float v[8][2];
#pragma unroll
            for (int j = 0; j < 8; j++) {
                v[j][0] = acc[mt][j][pr * 2]     + bvv[j][0];
                v[j][1] = acc[mt][j][pr * 2 + 1] + bvv[j][1];
            }
            if (mode < 2) {
                float ss = 0.0f;
#pragma unroll
                for (int j = 0; j < 8; j++) ss += v[j][0] * v[j][0] + v[j][1] * v[j][1];
                ss += __shfl_xor_sync(0xffffffffu, ss, 1);
                ss += __shfl_xor_sync(0xffffffffu, ss, 2);
                float r = rsqrtf(ss * (1.0f / 64.0f) + 1e-6f);
#pragma unroll
                for (int j = 0; j < 8; j++) {
                    v[j][0] *= r * wnv[j][0];
                    v[j][1] *= r * wnv[j][1];
                }
                const float* cr = cosT + s * 64;
                const float* sr = sinT + s * 64;
#pragma unroll
                for (int j = 0; j < 4; j++) {
#pragma unroll
                    for (int p = 0; p < 2; p++) {
                        int d = j * 8 + q2 + p;
                        float x0 = v[j][p], x1 = v[j + 4][p];
                        v[j][p]     = x0 * cr[d]      - x1 * sr[d];
                        v[j + 4][p] = x1 * cr[d + 32] + x0 * sr[d + 32];
                    }
                }
                if (mode == 0) {
#pragma unroll
                    for (int j = 0; j < 8; j++) { v[j][0] *= 0.125f; v[j][1] *= 0.125f; }
                }
            }
            __half* dp = dst + (((size_t)(bb * NHd + hh)) * Sn + s) * 64;
#pragma unroll
            for (int j = 0; j < 8; j++)
                *(uint32_t*)(dp + j * 8 + q2) = pack_h2(v[j][0], v[j][1]);
        }
    }
}

// ============================================================
// Standard HMMA GEMM (O-projection): fp32 out + bias
// ============================================================
__global__ __launch_bounds__(256, 2) void mm_hmma_kernel(
    const __half* __restrict__ Ah, const __half* __restrict__ Bh,
    const float* __restrict__ bias, float* __restrict__ Cm, int N, int K)
{
    extern __shared__ char sm[];
    const int t = threadIdx.x, wid = t >> 5, lane = t & 31;
    const int m0 = blockIdx.y * 128, n0 = blockIdx.x * 128;
    const uint32_t sbase = smem_u32(sm);

    const __half* gA = Ah + (size_t)m0 * K;
    const __half* gB = Bh + (size_t)n0 * K;

    const int warp_m = wid & 3;
    const int warp_n = wid >> 2;
    const int a_row = warp_m * 32 + (lane & 15);
    const int a_k8  = lane >> 4;
    const int b_row = warp_n * 64 + (lane & 7) + ((lane >> 4) << 3);
    const int b_k8  = (lane >> 3) & 1;

    float acc[2][8][4];
#pragma unroll
    for (int a = 0; a < 2; a++)
#pragma unroll
        for (int b = 0; b < 8; b++)
#pragma unroll
            for (int cq = 0; cq < 4; cq++) acc[a][b][cq] = 0.0f;

    GEMM_MAINLOOP(gA, gB, K);

    const int crow = m0 + warp_m * 32 + (lane >> 2);
    const int ccol = n0 + warp_n * 64 + (lane & 3) * 2;
#pragma unroll
    for (int j = 0; j < 8; j++) {
        int col = ccol + j * 8;
        float b0 = bias[col], b1 = bias[col + 1];
#pragma unroll
        for (int mt = 0; mt < 2; mt++) {
            int r0 = crow + mt * 16;
            float2 o0 = make_float2(acc[mt][j][0] + b0, acc[mt][j][1] + b1);
            float2 o1 = make_float2(acc[mt][j][2] + b0, acc[mt][j][3] + b1);
            *(float2*)(Cm + (size_t)r0 * N + col)       = o0;
            *(float2*)(Cm + (size_t)(r0 + 8) * N + col) = o1;
        }
    }
}

// ============================================================
// HMMA sliding-window attention, NO online softmax.
// |score| <= 8 guaranteed (rmsnorm => ||q||=||k||=8, q pre-scaled 1/8),
// so exp(s) in [3.4e-4, 2981]: no overflow, direct sum works.
// CTA: 256 threads (8 warps) = 2 q-heads sharing one KV head's tiles.
//   warps 0-3: head 2*hp, warps 4-7: head 2*hp+1; wm = wid&3 = 16-row group.
// ============================================================
__global__ __launch_bounds__(256) void attn_mma_kernel(
    const __half* __restrict__ qh, const __half* __restrict__ kh,
    const __half* __restrict__ vh, __half* __restrict__ att)
{
    __shared__ __half Qs[2][64 * 64];
    __shared__ __half Ks[2][64 * 64];
    __shared__ __half Vs[2][64 * 64];

    const int t = threadIdx.x, wid = t >> 5, lane = t & 31;
    const int wm = wid & 3, hsel = wid >> 2;
    const int q0 = blockIdx.x * 64;
    const int hp = blockIdx.y;           // head pair 0..7
    const int b  = blockIdx.z;
    const int h  = hp * 2 + hsel;
    const int hk = hp >> 1;              // shared kv head for both heads in pair

    const __half* Kg = kh + ((size_t)(b * HKVn + hk) * Sn) * 64;
    const __half* Vg = vh + ((size_t)(b * HKVn + hk) * Sn) * 64;

    const uint32_t sQ = smem_u32(Qs[hsel]);
    const uint32_t sK = smem_u32(Ks);
    const uint32_t sV = smem_u32(Vs);

    // load both heads' Q tiles (1024 x 16B chunks)
    {
        const uint32_t sQ0 = smem_u32(Qs);
        for (int i = t; i < 1024; i += 256) {
            int hs = i >> 9, row = (i >> 3) & 63, c = i & 7;
            uint32_t sw = (uint32_t)hs * 8192u + (uint32_t)row * 128u +
                          (uint32_t)((c ^ (row & 7)) << 4);
            cp16(sQ0 + sw,
                 qh + (((size_t)(b * Hn + hp * 2 + hs) * Sn) + q0 + row) * 64 + c * 8);
        }
    }

    int lo = 0; while (q0 - 128 + lo * 64 < 0) lo++;
    int hi = 4; while (q0 - 128 + hi * 64 + 64 > Sn) hi--;

#define PREFETCH(it, buf) do { \
    int kb_ = q0 - 128 + (it) * 64; \
    const __half* Kt_ = Kg + (size_t)kb_ * 64; \
    const __half* Vt_ = Vg + (size_t)kb_ * 64; \
    uint32_t sk_ = sK + (uint32_t)(buf) * 8192u; \
    uint32_t sv_ = sV + (uint32_t)(buf) * 8192u; \
    for (int i_ = t; i_ < 512; i_ += 256) { \
        int row_ = i_ >> 3, c_ = i_ & 7; \
        uint32_t sw_ = (uint32_t)row_ * 128u + (uint32_t)((c_ ^ (row_ & 7)) << 4); \
        cp16(sk_ + sw_, Kt_ + row_ * 64 + c_ * 8); \
        cp16(sv_ + sw_, Vt_ + row_ * 64 + c_ * 8); \
    } } while (0)

    PREFETCH(lo, 0);
    CP_COMMIT();

    const int arow = wm * 16 + (lane & 15);
    const int ak8  = lane >> 4;
    const int brow = (lane & 7) + ((lane >> 4) << 3);
    const int bk8  = (lane >> 3) & 1;
    const int vrow = (lane & 7) + (((lane >> 3) & 1) << 3);
    const int vc8  = lane >> 4;

    const int r0g = q0 + wm * 16 + (lane >> 2);
    const int r1g = r0g + 8;

    float acc[8][4];
#pragma unroll
    for (int g = 0; g < 8; g++)
#pragma unroll
        for (int e = 0; e < 4; e++) acc[g][e] = 0.0f;
    float l0 = 0.0f, l1 = 0.0f;          // per-lane partial sums

    uint32_t qf[4][4];
    bool qloaded = false;

    for (int it = lo; it <= hi; ++it) {
        const int buf = (it - lo) & 1;
        if (it < hi) { PREFETCH(it + 1, buf ^ 1); CP_COMMIT(); CP_WAIT1(); }
        else { CP_WAIT0(); }
        __syncthreads();

        if (!qloaded) {
#pragma unroll
            for (int kblk = 0; kblk < 4; kblk++) {
                uint32_t ad = sQ + (uint32_t)arow * 128u +
                              (uint32_t)(((kblk * 2 + ak8) ^ (arow & 7)) << 4);
                ldmx4(qf[kblk], ad);
            }
            qloaded = true;
        }

        const int kb = q0 - 128 + it * 64;
        const uint32_t sk = sK + (uint32_t)buf * 8192u;
        const uint32_t sv = sV + (uint32_t)buf * 8192u;
        const bool need_mask = (it == 0) || (it == 4);

        // ---- S = Q K^T ----
        float sc[8][4];
#pragma unroll
        for (int g = 0; g < 8; g++)
#pragma unroll
            for (int e = 0; e < 4; e++) sc[g][e] = 0.0f;
#pragma unroll
        for (int kblk = 0; kblk < 4; kblk++) {
#pragma unroll
            for (int g = 0; g < 4; g++) {
                int r = g * 16 + brow;
                uint32_t bd = sk + (uint32_t)r * 128u +
                              (uint32_t)(((kblk * 2 + bk8) ^ (r & 7)) << 4);
                uint32_t bf[4];
                ldmx4(bf, bd);
                mma16816(sc[2 * g],     qf[kblk], bf);
                mma16816(sc[2 * g + 1], qf[kblk], bf + 2);
            }
        }

        // ---- p = exp(s) (no max subtraction), mask -> 0, accumulate l ----
        uint32_t pf[8][2];
        if (need_mask) {
#pragma unroll
            for (int g = 0; g < 8; g++) {
                int j0 = kb + g * 8 + (lane & 3) * 2;
                int j1 = j0 + 1;
                float p0 = (abs(j0 - r0g) <= 128) ? __expf(sc[g][0]) : 0.0f;
                float p1 = (abs(j1 - r0g) <= 128) ? __expf(sc[g][1]) : 0.0f;
                float p2 = (abs(j0 - r1g) <= 128) ? __expf(sc[g][2]) : 0.0f;
                float p3 = (abs(j1 - r1g) <= 128) ? __expf(sc[g][3]) : 0.0f;
                l0 += p0 + p1;
                l1 += p2 + p3;
                pf[g][0] = pack_h2(p0, p1);
                pf[g][1] = pack_h2(p2, p3);
            }
        } else {
#pragma unroll
            for (int g = 0; g < 8; g++) {
                float p0 = __expf(sc[g][0]);
                float p1 = __expf(sc[g][1]);
                float p2 = __expf(sc[g][2]);
                float p3 = __expf(sc[g][3]);
                l0 += p0 + p1;
                l1 += p2 + p3;
                pf[g][0] = pack_h2(p0, p1);
                pf[g][1] = pack_h2(p2, p3);
            }
        }

        // ---- O += P V ----
#pragma unroll
        for (int jj = 0; jj < 4; jj++) {
            uint32_t a[4] = { pf[2 * jj][0], pf[2 * jj][1],
                              pf[2 * jj + 1][0], pf[2 * jj + 1][1] };
#pragma unroll
            for (int dg = 0; dg < 4; dg++) {
                int r = jj * 16 + vrow;
                uint32_t bd = sv + (uint32_t)r * 128u +
                              (uint32_t)(((dg * 2 + vc8) ^ (r & 7)) << 4);
                uint32_t bf[4];
                ldmx4t(bf, bd);
                mma16816(acc[2 * dg],     a, bf);
                mma16816(acc[2 * dg + 1], a, bf + 2);
            }
        }
        __syncthreads();
    }
#undef PREFETCH

    // ---- one final quad reduction of l, normalize, store ----
    l0 += __shfl_xor_sync(0xffffffffu, l0, 1);
    l0 += __shfl_xor_sync(0xffffffffu, l0, 2);
    l1 += __shfl_xor_sync(0xffffffffu, l1, 1);
    l1 += __shfl_xor_sync(0xffffffffu, l1, 2);
    const float i0 = 1.0f / l0, i1 = 1.0f / l1;
    const size_t base0 = ((size_t)(b * Sn) + r0g) * (Hn * DHn) + h * 64;
    const size_t base1 = ((size_t)(b * Sn) + r1g) * (Hn * DHn) + h * 64;
#pragma unroll
    for (int g = 0; g < 8; g++) {
        int d = g * 8 + (lane & 3) * 2;
        *(uint32_t*)(att + base0 + d) = pack_h2(acc[g][0] * i0, acc[g][1] * i0);
        *(uint32_t*)(att + base1 + d) = pack_h2(acc[g][2] * i1, acc[g][3] * i1);
    }
}

// ============================================================
extern "C" void kernel_launch(void* const* d_in, const int* in_sizes, int n_in,
                              void* d_out, int out_size)
{
    const float* x    = (const float*)d_in[0];
    const float* Wq   = (const float*)d_in[1];
    const float* bq   = (const float*)d_in[2];
    const float* Wk   = (const float*)d_in[3];
    const float* bk   = (const float*)d_in[4];
    const float* Wv   = (const float*)d_in[5];
    const float* bv   = (const float*)d_in[6];
    const float* Wo   = (const float*)d_in[7];
    const float* bo   = (const float*)d_in[8];
    const float* qn   = (const float*)d_in[9];
    const float* kn   = (const float*)d_in[10];
    const float* cosT = (const float*)d_in[11];
    const float* sinT = (const float*)d_in[12];
    float* out = (float*)d_out;

    __half *xh, *qh, *kh, *vh, *ah, *wqkv, *wo;
    cudaGetSymbolAddress((void**)&xh,   g_xh);
    cudaGetSymbolAddress((void**)&qh,   g_qh);
    cudaGetSymbolAddress((void**)&kh,   g_kh);
    cudaGetSymbolAddress((void**)&vh,   g_vh);
    cudaGetSymbolAddress((void**)&ah,   g_ah);
    cudaGetSymbolAddress((void**)&wqkv, g_wqkv);
    cudaGetSymbolAddress((void**)&wo,   g_wo);

    cudaFuncSetAttribute(mm_qkv_fused_kernel,
                         cudaFuncAttributeMaxDynamicSharedMemorySize, 65536);
    cudaFuncSetAttribute(mm_hmma_kernel,
                         cudaFuncAttributeMaxDynamicSharedMemorySize, 65536);
    const int DSMEM = 65536;

    const int n4x = Mtok * Dn / 4;
    cvt_kernel<<<(n4x + 255) / 256, 256>>>(x, xh, n4x);
    tcvt_kernel<<<dim3(1024 / 32, 1024 / 32), dim3(32, 8)>>>(Wq, wqkv, 1024, 1024);
    tcvt_kernel<<<dim3(256  / 32, 1024 / 32), dim3(32, 8)>>>(Wk, wqkv + 1024 * 1024, 1024, 256);
    tcvt_kernel<<<dim3(256  / 32, 1024 / 32), dim3(32, 8)>>>(Wv, wqkv + 1280 * 1024, 1024, 256);
    tcvt_kernel<<<dim3(1024 / 32, 1024 / 32), dim3(32, 8)>>>(Wo, wo, 1024, 1024);

    mm_qkv_fused_kernel<<<dim3(12, 128), 256, DSMEM>>>(
        xh, wqkv, bq, bk, bv, qn, kn, cosT, sinT, qh, kh, vh);

    attn_mma_kernel<<<dim3(Sn / 64, Hn / 2, Bn), 256>>>(qh, kh, vh, ah);

    mm_hmma_kernel<<<dim3(8, 128), 256, DSMEM>>>(ah, wo, bo, out, 1024, 1024);
}

// round 8
// speedup vs baseline: 7.4620x; 1.0761x over previous
#include <cuda_runtime.h>
#include <cuda_fp16.h>
#include <cstdint>

#define Bn   4
#define Sn   4096
#define Dn   1024
#define Hn   16
#define HKVn 4
#define DHn  64
#define Mtok (Bn*Sn)            // 16384

// Q pre-scale: (1/sqrt(64)) * log2(e) so attention can use ex2 directly
#define QSCALE 0.18033688011112042f

// ---- scratch ----
__device__ __half g_xh [Mtok * Dn];                 // x fp16
__device__ __half g_qh [Bn * Hn   * Sn * DHn];      // normed+roped+prescaled fp16
__device__ __half g_kh [Bn * HKVn * Sn * DHn];
__device__ __half g_vh [Bn * HKVn * Sn * DHn];
__device__ __half g_ah [Mtok * Hn * DHn];           // attention out fp16
__device__ __half g_wqkv[1536 * Dn];                // concat [Nq|Nk|Nv][K] fp16
__device__ __half g_wo  [Hn * DHn * Dn];            // [N,K] fp16

// ============================================================
// helpers
// ============================================================
__device__ __forceinline__ uint32_t smem_u32(const void* p) {
    uint32_t a;
    asm("{ .reg .u64 t; cvta.to.shared.u64 t, %1; cvt.u32.u64 %0, t; }" : "=r"(a) : "l"(p));
    return a;
}
__device__ __forceinline__ void cp16(uint32_t dst, const void* src) {
    asm volatile("cp.async.cg.shared.global [%0], [%1], 16;" :: "r"(dst), "l"(src));
}
#define CP_COMMIT() asm volatile("cp.async.commit_group;" ::: "memory")
#define CP_WAIT0()  asm volatile("cp.async.wait_group 0;" ::: "memory")
#define CP_WAIT1()  asm volatile("cp.async.wait_group 1;" ::: "memory")
#define CP_WAIT2()  asm volatile("cp.async.wait_group 2;" ::: "memory")

__device__ __forceinline__ void ldmx4(uint32_t* r, uint32_t addr) {
    asm volatile("ldmatrix.sync.aligned.m8n8.x4.shared.b16 {%0,%1,%2,%3}, [%4];"
        : "=r"(r[0]), "=r"(r[1]), "=r"(r[2]), "=r"(r[3]) : "r"(addr));
}
__device__ __forceinline__ void ldmx4t(uint32_t* r, uint32_t addr) {
    asm volatile("ldmatrix.sync.aligned.m8n8.x4.trans.shared.b16 {%0,%1,%2,%3}, [%4];"
        : "=r"(r[0]), "=r"(r[1]), "=r"(r[2]), "=r"(r[3]) : "r"(addr));
}
__device__ __forceinline__ void mma16816(float* c, const uint32_t* a, const uint32_t* b) {
    asm volatile("mma.sync.aligned.m16n8k16.row.col.f32.f16.f16.f32 "
        "{%0,%1,%2,%3}, {%4,%5,%6,%7}, {%8,%9}, {%0,%1,%2,%3};"
        : "+f"(c[0]), "+f"(c[1]), "+f"(c[2]), "+f"(c[3])
        : "r"(a[0]), "r"(a[1]), "r"(a[2]), "r"(a[3]), "r"(b[0]), "r"(b[1]));
}
__device__ __forceinline__ uint32_t pack_h2(float a, float b) {
    __half2 h = __floats2half2_rn(a, b);
    return *reinterpret_cast<uint32_t*>(&h);
}
__device__ __forceinline__ float ex2f(float x) {
    float y;
    asm("ex2.approx.ftz.f32 %0, %1;" : "=f"(y) : "f"(x));
    return y;
}

// ============================================================
// merged prep kernel: x fp32->fp16  +  4 weight transposes
// blocks [0,1024): Wq, [1024,1280): Wk, [1280,1536): Wv,
// [1536,2560): Wo, [2560, 2560+16384): x convert
// ============================================================
__global__ __launch_bounds__(256) void prep_kernel(
    const float* __restrict__ x,
    const float* __restrict__ Wq, const float* __restrict__ Wk,
    const float* __restrict__ Wv, const float* __restrict__ Wo,
    __half* __restrict__ xh, __half* __restrict__ wqkv, __half* __restrict__ wo)
{
    const int bid = blockIdx.x;
    const int t = threadIdx.x;

    if (bid >= 2560) {
        // x convert: exactly (Mtok*Dn/4)/256 = 16384 blocks
        int i = (bid - 2560) * 256 + t;
        float4 v = ((const float4*)x)[i];
        ushort4 o;
        o.x = __half_as_ushort(__float2half_rn(v.x));
        o.y = __half_as_ushort(__float2half_rn(v.y));
        o.z = __half_as_ushort(__float2half_rn(v.z));
        o.w = __half_as_ushort(__float2half_rn(v.w));
        ((ushort4*)xh)[i] = o;
        return;
    }

    // transpose+convert W[K=1024, N] -> dst[N, 1024]
    __shared__ float tile[32][33];
    const float* W;
    __half* dst;
    int N, base;
    if (bid < 1024)      { W = Wq; dst = wqkv;               N = 1024; base = bid; }
    else if (bid < 1280) { W = Wk; dst = wqkv + 1024 * 1024; N = 256;  base = bid - 1024; }
    else if (bid < 1536) { W = Wv; dst = wqkv + 1280 * 1024; N = 256;  base = bid - 1280; }
    else                 { W = Wo; dst = wo;                 N = 1024; base = bid - 1536; }

    const int nblk = N >> 5;
    const int n0 = (base % nblk) * 32;
    const int k0 = (base / nblk) * 32;
    const int tx = t & 31, ty = t >> 5;     // 32 x 8

    for (int r = ty; r < 32; r += 8)
        tile[r][tx] = W[(size_t)(k0 + r) * N + n0 + tx];
    __syncthreads();
    for (int r = ty; r < 32; r += 8)
        dst[(size_t)(n0 + r) * 1024 + k0 + tx] = __float2half_rn(tile[tx][r]);
}

// ============================================================
// GEMM mainloop: 128x128 tile, BK=32, 4-stage ring, 2 chunks per
// sync window (wait_group 2) -> half the barriers.
// ============================================================
#define STAGE_LOAD_CH(buf, c) do { \
    uint32_t sb_ = sbase + (uint32_t)(buf) * 16384u; \
    _Pragma("unroll") \
    for (int i_ = 0; i_ < 2; i_++) { \
        int row_ = i_ * 64 + lr; \
        uint32_t sw_ = (uint32_t)row_ * 64u + (uint32_t)((lc16 ^ ((row_ >> 1) & 3)) << 4); \
        size_t go_ = (size_t)row_ * (size_t)Kd + (size_t)(c) * 32 + lc16 * 8; \
        cp16(sb_ + sw_,         gA + go_); \
        cp16(sb_ + 8192u + sw_, gB + go_); \
    } } while (0)

#define GEMM_COMPUTE_CH(cc) do { \
    const uint32_t sb = sbase + (uint32_t)((cc) & 3) * 16384u; \
    _Pragma("unroll") \
    for (int ks = 0; ks < 2; ks++) { \
        uint32_t ahf[2][4], bhf[4][4]; \
        _Pragma("unroll") \
        for (int mt = 0; mt < 2; mt++) { \
            int r = a_row + mt * 16; \
            uint32_t ad = sb + (uint32_t)r * 64u + \
                          (uint32_t)(((ks * 2 + a_k8) ^ ((r >> 1) & 3)) << 4); \
            ldmx4(ahf[mt], ad); \
        } \
        _Pragma("unroll") \
        for (int g = 0; g < 4; g++) { \
            int r = b_row + g * 16; \
            uint32_t bd = sb + 8192u + (uint32_t)r * 64u + \
                          (uint32_t)(((ks * 2 + b_k8) ^ ((r >> 1) & 3)) << 4); \
            ldmx4(bhf[g], bd); \
        } \
        _Pragma("unroll") \
        for (int mt = 0; mt < 2; mt++) \
            _Pragma("unroll") \
            for (int j = 0; j < 8; j++) \
                mma16816(acc[mt][j], ahf[mt], &bhf[j >> 1][(j & 1) * 2]); \
    } } while (0)

#define GEMM_MAINLOOP(Agl, Bgl, Kdim) do { \
    const __half* gA = (Agl); \
    const __half* gB = (Bgl); \
    const int Kd = (Kdim); \
    const int lr = t >> 2; \
    const int lc16 = t & 3; \
    const int NCH = Kd >> 5; \
    _Pragma("unroll") \
    for (int s = 0; s < 4; s++) { STAGE_LOAD_CH(s, s); CP_COMMIT(); } \
    for (int c = 0; c < NCH; c += 2) { \
        CP_WAIT2(); \
        __syncthreads(); \
        GEMM_COMPUTE_CH(c); \
        GEMM_COMPUTE_CH(c + 1); \
        __syncthreads(); \
        if (c + 4 < NCH) STAGE_LOAD_CH(c & 3, c + 4); \
        CP_COMMIT(); \
        if (c + 5 < NCH) STAGE_LOAD_CH((c + 1) & 3, c + 5); \
        CP_COMMIT(); \
    } } while (0)

// ============================================================
// Fused QKV GEMM + bias + RMSNorm + RoPE + fp16 transpose store.
// ============================================================
__global__ __launch_bounds__(256, 2) void mm_qkv_fused_kernel(
    const __half* __restrict__ Ah, const __half* __restrict__ Bw,
    const float* __restrict__ bq, const float* __restrict__ bk,
    const float* __restrict__ bv,
    const float* __restrict__ qnw, const float* __restrict__ knw,
    const float* __restrict__ cosT, const float* __restrict__ sinT,
    __half* __restrict__ qh, __half* __restrict__ kh, __half* __restrict__ vh)
{
    extern __shared__ char sm[];
    const int t = threadIdx.x, wid = t >> 5, lane = t & 31;
    const int m0 = blockIdx.y * 128, n0 = blockIdx.x * 128;
    const uint32_t sbase = smem_u32(sm);

    const int warp_m = wid & 3;
    const int warp_n = wid >> 2;
    const int a_row = warp_m * 32 + (lane & 15);
    const int a_k8  = lane >> 4;
    const int b_row = warp_n * 64 + (lane & 7) + ((lane >> 4) << 3);
    const int b_k8  = (lane >> 3) & 1;

    float acc[2][8][4];
#pragma unroll
    for (int a = 0; a < 2; a++)
#pragma unroll
        for (int b = 0; b < 8; b++)
#pragma unroll
            for (int cq = 0; cq < 4; cq++) acc[a][b][cq] = 0.0f;

    GEMM_MAINLOOP(Ah + (size_t)m0 * Dn, Bw + (size_t)n0 * Dn, Dn);

    const int gc = n0 + warp_n * 64;
    const int q2 = (lane & 3) * 2;

    int mode, hh, NHd;
    __half* dst;
    const float* bptr;
    const float* wn = qnw;
    if (gc < 1024)      { mode = 0; hh = gc >> 6;          dst = qh; bptr = bq + gc;          wn = qnw; NHd = Hn;  }
    else if (gc < 1280) { mode = 1; hh = (gc - 1024) >> 6; dst = kh; bptr = bk + (gc - 1024); wn = knw; NHd = HKVn; }
    else                { mode = 2; hh = (gc - 1280) >> 6; dst = vh; bptr = bv + (gc - 1280); NHd = HKVn; }

    float bvv[8][2], wnv[8][2];
#pragma unroll
    for (int j = 0; j < 8; j++) {
        bvv[j][0] = bptr[j * 8 + q2];
        bvv[j][1] = bptr[j * 8 + q2 + 1];
    }
    if (mode < 2) {
#pragma unroll
        for (int j = 0; j < 8; j++) {
            wnv[j][0] = wn[j * 8 + q2];
            wnv[j][1] = wn[j * 8 + q2 + 1];
        }
    }

#pragma unroll
    for (int mt = 0; mt < 2; mt++) {
#pragma unroll
        for (int pr = 0; pr < 2; pr++) {
            const int row = m0 + warp_m * 32 + (lane >> 2) + mt * 16 + pr * 8;
            const int s  = row & (Sn - 1);
            const int bb = row >> 12;
            float v[8][2];
#pragma unroll
            for (int j = 0; j < 8; j++) {
                v[j][0] = acc[mt][j][pr * 2]     + bvv[j][0];
                v[j][1] = acc[mt][j][pr * 2 + 1] + bvv[j][1];
            }
            if (mode < 2) {
                float ss = 0.0f;
#pragma unroll
                for (int j = 0; j < 8; j++) ss += v[j][0] * v[j][0] + v[j][1] * v[j][1];
                ss += __shfl_xor_sync(0xffffffffu, ss, 1);
                ss += __shfl_xor_sync(0xffffffffu, ss, 2);
                float r = rsqrtf(ss * (1.0f / 64.0f) + 1e-6f);
#pragma unroll
                for (int j = 0; j < 8; j++) {
                    v[j][0] *= r * wnv[j][0];
                    v[j][1] *= r * wnv[j][1];
                }
                const float* cr = cosT + s * 64;
                const float* sr = sinT + s * 64;
#pragma unroll
                for (int j = 0; j < 4; j++) {
#pragma unroll
                    for (int p = 0; p < 2; p++) {
                        int d = j * 8 + q2 + p;
                        float x0 = v[j][p], x1 = v[j + 4][p];
                        v[j][p]     = x0 * cr[d]      - x1 * sr[d];
                        v[j + 4][p] = x1 * cr[d + 32] + x0 * sr[d + 32];
                    }
                }
                if (mode == 0) {
#pragma unroll
                    for (int j = 0; j < 8; j++) { v[j][0] *= QSCALE; v[j][1] *= QSCALE; }
                }
            }
            __half* dp = dst + (((size_t)(bb * NHd + hh)) * Sn + s) * 64;
#pragma unroll
            for (int j = 0; j < 8; j++)
                *(uint32_t*)(dp + j * 8 + q2) = pack_h2(v[j][0], v[j][1]);
        }
    }
}

// ============================================================
// Standard HMMA GEMM (O-projection): fp32 out + bias
// ============================================================
__global__ __launch_bounds__(256, 2) void mm_hmma_kernel(
    const __half* __restrict__ Ah, const __half* __restrict__ Bh,
    const float* __restrict__ bias, float* __restrict__ Cm, int N, int K)
{
    extern __shared__ char sm[];
    const int t = threadIdx.x, wid = t >> 5, lane = t & 31;
    const int m0 = blockIdx.y * 128, n0 = blockIdx.x * 128;
    const uint32_t sbase = smem_u32(sm);

    const int warp_m = wid & 3;
    const int warp_n = wid >> 2;
    const int a_row = warp_m * 32 + (lane & 15);
    const int a_k8  = lane >> 4;
    const int b_row = warp_n * 64 + (lane & 7) + ((lane >> 4) << 3);
    const int b_k8  = (lane >> 3) & 1;

    float acc[2][8][4];
#pragma unroll
    for (int a = 0; a < 2; a++)
#pragma unroll
        for (int b = 0; b < 8; b++)
#pragma unroll
            for (int cq = 0; cq < 4; cq++) acc[a][b][cq] = 0.0f;

    GEMM_MAINLOOP(Ah + (size_t)m0 * K, Bh + (size_t)n0 * K, K);

    const int crow = m0 + warp_m * 32 + (lane >> 2);
    const int ccol = n0 + warp_n * 64 + (lane & 3) * 2;
#pragma unroll
    for (int j = 0; j < 8; j++) {
        int col = ccol + j * 8;
        float b0 = bias[col], b1 = bias[col + 1];
#pragma unroll
        for (int mt = 0; mt < 2; mt++) {
            int r0 = crow + mt * 16;
            float2 o0 = make_float2(acc[mt][j][0] + b0, acc[mt][j][1] + b1);
            float2 o1 = make_float2(acc[mt][j][2] + b0, acc[mt][j][3] + b1);
            *(float2*)(Cm + (size_t)r0 * N + col)       = o0;
            *(float2*)(Cm + (size_t)(r0 + 8) * N + col) = o1;
        }
    }
}

// ============================================================
// HMMA sliding-window attention (scores pre-scaled to base-2, ex2).
// CTA: 256 threads = 2 q-heads sharing one KV head's tiles.
// ============================================================
__global__ __launch_bounds__(256) void attn_mma_kernel(
    const __half* __restrict__ qh, const __half* __restrict__ kh,
    const __half* __restrict__ vh, __half* __restrict__ att)
{
    __shared__ __half Qs[2][64 * 64];
    __shared__ __half Ks[2][64 * 64];
    __shared__ __half Vs[2][64 * 64];

    const int t = threadIdx.x, wid = t >> 5, lane = t & 31;
    const int wm = wid & 3, hsel = wid >> 2;
    const int q0 = blockIdx.x * 64;
    const int hp = blockIdx.y;
    const int b  = blockIdx.z;
    const int h  = hp * 2 + hsel;
    const int hk = hp >> 1;

    const __half* Kg = kh + ((size_t)(b * HKVn + hk) * Sn) * 64;
    const __half* Vg = vh + ((size_t)(b * HKVn + hk) * Sn) * 64;

    const uint32_t sQ = smem_u32(Qs[hsel]);
    const uint32_t sK = smem_u32(Ks);
    const uint32_t sV = smem_u32(Vs);

    {
        const uint32_t sQ0 = smem_u32(Qs);
        for (int i = t; i < 1024; i += 256) {
            int hs = i >> 9, row = (i >> 3) & 63, c = i & 7;
            uint32_t sw = (uint32_t)hs * 8192u + (uint32_t)row * 128u +
                          (uint32_t)((c ^ (row & 7)) << 4);
            cp16(sQ0 + sw,
                 qh + (((size_t)(b * Hn + hp * 2 + hs) * Sn) + q0 + row) * 64 + c * 8);
        }
    }

    int lo = 0; while (q0 - 128 + lo * 64 < 0) lo++;
    int hi = 4; while (q0 - 128 + hi * 64 + 64 > Sn) hi--;

#define PREFETCH(it, buf) do { \
    int kb_ = q0 - 128 + (it) * 64; \
    const __half* Kt_ = Kg + (size_t)kb_ * 64; \
    const __half* Vt_ = Vg + (size_t)kb_ * 64; \
    uint32_t sk_ = sK + (uint32_t)(buf) * 8192u; \
    uint32_t sv_ = sV + (uint32_t)(buf) * 8192u; \
    for (int i_ = t; i_ < 512; i_ += 256) { \
        int row_ = i_ >> 3, c_ = i_ & 7; \
        uint32_t sw_ = (uint32_t)row_ * 128u + (uint32_t)((c_ ^ (row_ & 7)) << 4); \
        cp16(sk_ + sw_, Kt_ + row_ * 64 + c_ * 8); \
        cp16(sv_ + sw_, Vt_ + row_ * 64 + c_ * 8); \
    } } while (0)

    PREFETCH(lo, 0);
    CP_COMMIT();

    const int arow = wm * 16 + (lane & 15);
    const int ak8  = lane >> 4;
    const int brow = (lane & 7) + ((lane >> 4) << 3);
    const int bk8  = (lane >> 3) & 1;
    const int vrow = (lane & 7) + (((lane >> 3) & 1) << 3);
    const int vc8  = lane >> 4;

    const int r0g = q0 + wm * 16 + (lane >> 2);
    const int r1g = r0g + 8;

    float acc[8][4];
#pragma unroll
    for (int g = 0; g < 8; g++)
#pragma unroll
        for (int e = 0; e < 4; e++) acc[g][e] = 0.0f;
    float l0 = 0.0f, l1 = 0.0f;

    uint32_t qf[4][4];
    bool qloaded = false;

    for (int it = lo; it <= hi; ++it) {
        const int buf = (it - lo) & 1;
        if (it < hi) { PREFETCH(it + 1, buf ^ 1); CP_COMMIT(); CP_WAIT1(); }
        else { CP_WAIT0(); }
        __syncthreads();

        if (!qloaded) {
#pragma unroll
            for (int kblk = 0; kblk < 4; kblk++) {
                uint32_t ad = sQ + (uint32_t)arow * 128u +
                              (uint32_t)(((kblk * 2 + ak8) ^ (arow & 7)) << 4);
                ldmx4(qf[kblk], ad);
            }
            qloaded = true;
        }

        const int kb = q0 - 128 + it * 64;
        const uint32_t sk = sK + (uint32_t)buf * 8192u;
        const uint32_t sv = sV + (uint32_t)buf * 8192u;
        const bool need_mask = (it == 0) || (it == 4);

        float sc[8][4];
#pragma unroll
        for (int g = 0; g < 8; g++)
#pragma unroll
            for (int e = 0; e < 4; e++) sc[g][e] = 0.0f;
#pragma unroll
        for (int kblk = 0; kblk < 4; kblk++) {
#pragma unroll
            for (int g = 0; g < 4; g++) {
                int r = g * 16 + brow;
                uint32_t bd = sk + (uint32_t)r * 128u +
                              (uint32_t)(((kblk * 2 + bk8) ^ (r & 7)) << 4);
                uint32_t bf[4];
                ldmx4(bf, bd);
                mma16816(sc[2 * g],     qf[kblk], bf);
                mma16816(sc[2 * g + 1], qf[kblk], bf + 2);
            }
        }

        uint32_t pf[8][2];
        if (need_mask) {
#pragma unroll
            for (int g = 0; g < 8; g++) {
                int j0 = kb + g * 8 + (lane & 3) * 2;
                int j1 = j0 + 1;
                float p0 = (abs(j0 - r0g) <= 128) ? ex2f(sc[g][0]) : 0.0f;
                float p1 = (abs(j1 - r0g) <= 128) ? ex2f(sc[g][1]) : 0.0f;
                float p2 = (abs(j0 - r1g) <= 128) ? ex2f(sc[g][2]) : 0.0f;
                float p3 = (abs(j1 - r1g) <= 128) ? ex2f(sc[g][3]) : 0.0f;
                l0 += p0 + p1;
                l1 += p2 + p3;
                pf[g][0] = pack_h2(p0, p1);
                pf[g][1] = pack_h2(p2, p3);
            }
        } else {
#pragma unroll
            for (int g = 0; g < 8; g++) {
                float p0 = ex2f(sc[g][0]);
                float p1 = ex2f(sc[g][1]);
                float p2 = ex2f(sc[g][2]);
                float p3 = ex2f(sc[g][3]);
                l0 += p0 + p1;
                l1 += p2 + p3;
                pf[g][0] = pack_h2(p0, p1);
                pf[g][1] = pack_h2(p2, p3);
            }
        }

#pragma unroll
        for (int jj = 0; jj < 4; jj++) {
            uint32_t a[4] = { pf[2 * jj][0], pf[2 * jj][1],
                              pf[2 * jj + 1][0], pf[2 * jj + 1][1] };
#pragma unroll
            for (int dg = 0; dg < 4; dg++) {
                int r = jj * 16 + vrow;
                uint32_t bd = sv + (uint32_t)r * 128u +
                              (uint32_t)(((dg * 2 + vc8) ^ (r & 7)) << 4);
                uint32_t bf[4];
                ldmx4t(bf, bd);
                mma16816(acc[2 * dg],     a, bf);
                mma16816(acc[2 * dg + 1], a, bf + 2);
            }
        }
        __syncthreads();
    }
#undef PREFETCH

    l0 += __shfl_xor_sync(0xffffffffu, l0, 1);
    l0 += __shfl_xor_sync(0xffffffffu, l0, 2);
    l1 += __shfl_xor_sync(0xffffffffu, l1, 1);
    l1 += __shfl_xor_sync(0xffffffffu, l1, 2);
    const float i0 = 1.0f / l0, i1 = 1.0f / l1;
    const size_t base0 = ((size_t)(b * Sn) + r0g) * (Hn * DHn) + h * 64;
    const size_t base1 = ((size_t)(b * Sn) + r1g) * (Hn * DHn) + h * 64;
#pragma unroll
    for (int g = 0; g < 8; g++) {
        int d = g * 8 + (lane & 3) * 2;
        *(uint32_t*)(att + base0 + d) = pack_h2(acc[g][0] * i0, acc[g][1] * i0);
        *(uint32_t*)(att + base1 + d) = pack_h2(acc[g][2] * i1, acc[g][3] * i1);
    }
}

// ============================================================
extern "C" void kernel_launch(void* const* d_in, const int* in_sizes, int n_in,
                              void* d_out, int out_size)
{
    const float* x    = (const float*)d_in[0];
    const float* Wq   = (const float*)d_in[1];
    const float* bq   = (const float*)d_in[2];
    const float* Wk   = (const float*)d_in[3];
    const float* bk   = (const float*)d_in[4];
    const float* Wv   = (const float*)d_in[5];
    const float* bv   = (const float*)d_in[6];
    const float* Wo   = (const float*)d_in[7];
    const float* bo   = (const float*)d_in[8];
    const float* qn   = (const float*)d_in[9];
    const float* kn   = (const float*)d_in[10];
    const float* cosT = (const float*)d_in[11];
    const float* sinT = (const float*)d_in[12];
    float* out = (float*)d_out;

    __half *xh, *qh, *kh, *vh, *ah, *wqkv, *wo;
    cudaGetSymbolAddress((void**)&xh,   g_xh);
    cudaGetSymbolAddress((void**)&qh,   g_qh);
    cudaGetSymbolAddress((void**)&kh,   g_kh);
    cudaGetSymbolAddress((void**)&vh,   g_vh);
    cudaGetSymbolAddress((void**)&ah,   g_ah);
    cudaGetSymbolAddress((void**)&wqkv, g_wqkv);
    cudaGetSymbolAddress((void**)&wo,   g_wo);

    cudaFuncSetAttribute(mm_qkv_fused_kernel,
                         cudaFuncAttributeMaxDynamicSharedMemorySize, 65536);
    cudaFuncSetAttribute(mm_hmma_kernel,
                         cudaFuncAttributeMaxDynamicSharedMemorySize, 65536);
    const int DSMEM = 65536;

    // one merged prep launch: x convert + all weight transposes
    prep_kernel<<<2560 + 16384, 256>>>(x, Wq, Wk, Wv, Wo, xh, wqkv, wo);

    mm_qkv_fused_kernel<<<dim3(12, 128), 256, DSMEM>>>(
        xh, wqkv, bq, bk, bv, qn, kn, cosT, sinT, qh, kh, vh);

    attn_mma_kernel<<<dim3(Sn / 64, Hn / 2, Bn), 256>>>(qh, kh, vh, ah);

    mm_hmma_kernel<<<dim3(8, 128), 256, DSMEM>>>(ah, wo, bo, out, 1024, 1024);
}

// round 9
// speedup vs baseline: 7.5126x; 1.0068x over previous
#include <cuda_runtime.h>
#include <cuda_fp16.h>
#include <cstdint>

#define Bn   4
#define Sn   4096
#define Dn   1024
#define Hn   16
#define HKVn 4
#define DHn  64
#define Mtok (Bn*Sn)            // 16384

// Q pre-scale: (1/sqrt(64)) * log2(e) so attention can use ex2 directly
#define QSCALE 0.18033688011112042f

// ---- scratch ----
__device__ __half g_xh [Mtok * Dn];
__device__ __half g_qh [Bn * Hn   * Sn * DHn];
__device__ __half g_kh [Bn * HKVn * Sn * DHn];
__device__ __half g_vh [Bn * HKVn * Sn * DHn];
__device__ __half g_ah [Mtok * Hn * DHn];
__device__ __half g_wqkv[1536 * Dn];
__device__ __half g_wo  [Hn * DHn * Dn];

// ============================================================
// helpers
// ============================================================
__device__ __forceinline__ uint32_t smem_u32(const void* p) {
    uint32_t a;
    asm("{ .reg .u64 t; cvta.to.shared.u64 t, %1; cvt.u32.u64 %0, t; }" : "=r"(a) : "l"(p));
    return a;
}
__device__ __forceinline__ void cp16(uint32_t dst, const void* src) {
    asm volatile("cp.async.cg.shared.global [%0], [%1], 16;" :: "r"(dst), "l"(src));
}
#define CP_COMMIT() asm volatile("cp.async.commit_group;" ::: "memory")
#define CP_WAIT0()  asm volatile("cp.async.wait_group 0;" ::: "memory")
#define CP_WAIT1()  asm volatile("cp.async.wait_group 1;" ::: "memory")
#define CP_WAIT2()  asm volatile("cp.async.wait_group 2;" ::: "memory")

__device__ __forceinline__ void ldmx4(uint32_t* r, uint32_t addr) {
    asm volatile("ldmatrix.sync.aligned.m8n8.x4.shared.b16 {%0,%1,%2,%3}, [%4];"
        : "=r"(r[0]), "=r"(r[1]), "=r"(r[2]), "=r"(r[3]) : "r"(addr));
}
__device__ __forceinline__ void ldmx4t(uint32_t* r, uint32_t addr) {
    asm volatile("ldmatrix.sync.aligned.m8n8.x4.trans.shared.b16 {%0,%1,%2,%3}, [%4];"
        : "=r"(r[0]), "=r"(r[1]), "=r"(r[2]), "=r"(r[3]) : "r"(addr));
}
__device__ __forceinline__ void mma16816(float* c, const uint32_t* a, const uint32_t* b) {
    asm volatile("mma.sync.aligned.m16n8k16.row.col.f32.f16.f16.f32 "
        "{%0,%1,%2,%3}, {%4,%5,%6,%7}, {%8,%9}, {%0,%1,%2,%3};"
        : "+f"(c[0]), "+f"(c[1]), "+f"(c[2]), "+f"(c[3])
        : "r"(a[0]), "r"(a[1]), "r"(a[2]), "r"(a[3]), "r"(b[0]), "r"(b[1]));
}
__device__ __forceinline__ uint32_t pack_h2(float a, float b) {
    __half2 h = __floats2half2_rn(a, b);
    return *reinterpret_cast<uint32_t*>(&h);
}
__device__ __forceinline__ float ex2f(float x) {
    float y;
    asm("ex2.approx.ftz.f32 %0, %1;" : "=f"(y) : "f"(x));
    return y;
}

// ============================================================
// merged prep kernel: x fp32->fp16  +  4 weight transposes
// ============================================================
__global__ __launch_bounds__(256) void prep_kernel(
    const float* __restrict__ x,
    const float* __restrict__ Wq, const float* __restrict__ Wk,
    const float* __restrict__ Wv, const float* __restrict__ Wo,
    __half* __restrict__ xh, __half* __restrict__ wqkv, __half* __restrict__ wo)
{
    const int bid = blockIdx.x;
    const int t = threadIdx.x;

    if (bid >= 2560) {
        int i = (bid - 2560) * 256 + t;
        float4 v = ((const float4*)x)[i];
        ushort4 o;
        o.x = __half_as_ushort(__float2half_rn(v.x));
        o.y = __half_as_ushort(__float2half_rn(v.y));
        o.z = __half_as_ushort(__float2half_rn(v.z));
        o.w = __half_as_ushort(__float2half_rn(v.w));
        ((ushort4*)xh)[i] = o;
        return;
    }

    __shared__ float tile[32][33];
    const float* W;
    __half* dst;
    int N, base;
    if (bid < 1024)      { W = Wq; dst = wqkv;               N = 1024; base = bid; }
    else if (bid < 1280) { W = Wk; dst = wqkv + 1024 * 1024; N = 256;  base = bid - 1024; }
    else if (bid < 1536) { W = Wv; dst = wqkv + 1280 * 1024; N = 256;  base = bid - 1280; }
    else                 { W = Wo; dst = wo;                 N = 1024; base = bid - 1536; }

    const int nblk = N >> 5;
    const int n0 = (base % nblk) * 32;
    const int k0 = (base / nblk) * 32;
    const int tx = t & 31, ty = t >> 5;

    for (int r = ty; r < 32; r += 8)
        tile[r][tx] = W[(size_t)(k0 + r) * N + n0 + tx];
    __syncthreads();
    for (int r = ty; r < 32; r += 8)
        dst[(size_t)(n0 + r) * 1024 + k0 + tx] = __float2half_rn(tile[tx][r]);
}

// ============================================================
// GEMM mainloop: 128x128 CTA tile, 4 warps, 64x64 warp tile.
// BK=32, 4-stage cp.async ring, 2 chunks per sync window.
// Per k16-step per warp: 8 LDSM.x4 feed 32 MMAs (128 B/MMA).
// ============================================================
#define STAGE_LOAD_CH(buf, c) do { \
    uint32_t sb_ = sbase + (uint32_t)(buf) * 16384u; \
    _Pragma("unroll") \
    for (int i_ = 0; i_ < 4; i_++) { \
        int idx_ = t + i_ * 128; \
        int row_ = idx_ >> 2; \
        int lc_  = idx_ & 3; \
        uint32_t sw_ = (uint32_t)row_ * 64u + (uint32_t)((lc_ ^ ((row_ >> 1) & 3)) << 4); \
        size_t go_ = (size_t)row_ * (size_t)Kd + (size_t)(c) * 32 + lc_ * 8; \
        cp16(sb_ + sw_,         gA + go_); \
        cp16(sb_ + 8192u + sw_, gB + go_); \
    } } while (0)

#define GEMM_COMPUTE_CH(cc) do { \
    const uint32_t sb = sbase + (uint32_t)((cc) & 3) * 16384u; \
    _Pragma("unroll") \
    for (int ks = 0; ks < 2; ks++) { \
        uint32_t ahf[4][4], bhf[4][4]; \
        _Pragma("unroll") \
        for (int mt = 0; mt < 4; mt++) { \
            int r = a_row + mt * 16; \
            uint32_t ad = sb + (uint32_t)r * 64u + \
                          (uint32_t)(((ks * 2 + a_k8) ^ ((r >> 1) & 3)) << 4); \
            ldmx4(ahf[mt], ad); \
        } \
        _Pragma("unroll") \
        for (int g = 0; g < 4; g++) { \
            int r = b_row + g * 16; \
            uint32_t bd = sb + 8192u + (uint32_t)r * 64u + \
                          (uint32_t)(((ks * 2 + b_k8) ^ ((r >> 1) & 3)) << 4); \
            ldmx4(bhf[g], bd); \
        } \
        _Pragma("unroll") \
        for (int mt = 0; mt < 4; mt++) \
            _Pragma("unroll") \
            for (int j = 0; j < 8; j++) \
                mma16816(acc[mt][j], ahf[mt], &bhf[j >> 1][(j & 1) * 2]); \
    } } while (0)

#define GEMM_MAINLOOP(Agl, Bgl, Kdim) do { \
    const __half* gA = (Agl); \
    const __half* gB = (Bgl); \
    const int Kd = (Kdim); \
    const int NCH = Kd >> 5; \
    _Pragma("unroll") \
    for (int s = 0; s < 4; s++) { STAGE_LOAD_CH(s, s); CP_COMMIT(); } \
    for (int c = 0; c < NCH; c += 2) { \
        CP_WAIT2(); \
        __syncthreads(); \
        GEMM_COMPUTE_CH(c); \
        GEMM_COMPUTE_CH(c + 1); \
        __syncthreads(); \
        if (c + 4 < NCH) STAGE_LOAD_CH(c & 3, c + 4); \
        CP_COMMIT(); \
        if (c + 5 < NCH) STAGE_LOAD_CH((c + 1) & 3, c + 5); \
        CP_COMMIT(); \
    } } while (0)

// ============================================================
// Fused QKV GEMM + bias + RMSNorm + RoPE + fp16 transpose store.
// 128 threads; warp_m = wid&1 (64 rows), warp_n = wid>>1 (64 cols = 1 head).
// ============================================================
__global__ __launch_bounds__(128, 2) void mm_qkv_fused_kernel(
    const __half* __restrict__ Ah, const __half* __restrict__ Bw,
    const float* __restrict__ bq, const float* __restrict__ bk,
    const float* __restrict__ bv,
    const float* __restrict__ qnw, const float* __restrict__ knw,
    const float* __restrict__ cosT, const float* __restrict__ sinT,
    __half* __restrict__ qh, __half* __restrict__ kh, __half* __restrict__ vh)
{
    extern __shared__ char sm[];
    const int t = threadIdx.x, wid = t >> 5, lane = t & 31;
    const int m0 = blockIdx.y * 128, n0 = blockIdx.x * 128;
    const uint32_t sbase = smem_u32(sm);

    const int warp_m = wid & 1;
    const int warp_n = wid >> 1;
    const int a_row = warp_m * 64 + (lane & 15);
    const int a_k8  = lane >> 4;
    const int b_row = warp_n * 64 + (lane & 7) + ((lane >> 4) << 3);
    const int b_k8  = (lane >> 3) & 1;

    float acc[4][8][4];
#pragma unroll
    for (int a = 0; a < 4; a++)
#pragma unroll
        for (int b = 0; b < 8; b++)
#pragma unroll
            for (int cq = 0; cq < 4; cq++) acc[a][b][cq] = 0.0f;

    GEMM_MAINLOOP(Ah + (size_t)m0 * Dn, Bw + (size_t)n0 * Dn, Dn);

    const int gc = n0 + warp_n * 64;
    const int q2 = (lane & 3) * 2;

    int mode, hh, NHd;
    __half* dst;
    const float* bptr;
    const float* wn = qnw;
    if (gc < 1024)      { mode = 0; hh = gc >> 6;          dst = qh; bptr = bq + gc;          wn = qnw; NHd = Hn;  }
    else if (gc < 1280) { mode = 1; hh = (gc - 1024) >> 6; dst = kh; bptr = bk + (gc - 1024); wn = knw; NHd = HKVn; }
    else                { mode = 2; hh = (gc - 1280) >> 6; dst = vh; bptr = bv + (gc - 1280); NHd = HKVn; }

    float bvv[8][2], wnv[8][2];
#pragma unroll
    for (int j = 0; j < 8; j++) {
        bvv[j][0] = bptr[j * 8 + q2];
        bvv[j][1] = bptr[j * 8 + q2 + 1];
    }
    if (mode < 2) {
#pragma unroll
        for (int j = 0; j < 8; j++) {
            wnv[j][0] = wn[j * 8 + q2];
            wnv[j][1] = wn[j * 8 + q2 + 1];
        }
    }

#pragma unroll
    for (int mt = 0; mt < 4; mt++) {
#pragma unroll
        for (int pr = 0; pr < 2; pr++) {
            const int row = m0 + warp_m * 64 + (lane >> 2) + mt * 16 + pr * 8;
            const int s  = row & (Sn - 1);
            const int bb = row >> 12;
            float v[8][2];
#pragma unroll
            for (int j = 0; j < 8; j++) {
                v[j][0] = acc[mt][j][pr * 2]     + bvv[j][0];
                v[j][1] = acc[mt][j][pr * 2 + 1] + bvv[j][1];
            }
            if (mode < 2) {
                float ss = 0.0f;
#pragma unroll
                for (int j = 0; j < 8; j++) ss += v[j][0] * v[j][0] + v[j][1] * v[j][1];
                ss += __shfl_xor_sync(0xffffffffu, ss, 1);
                ss += __shfl_xor_sync(0xffffffffu, ss, 2);
                float r = rsqrtf(ss * (1.0f / 64.0f) + 1e-6f);
#pragma unroll
                for (int j = 0; j < 8; j++) {
                    v[j][0] *= r * wnv[j][0];
                    v[j][1] *= r * wnv[j][1];
                }
                const float* cr = cosT + s * 64;
                const float* sr = sinT + s * 64;
#pragma unroll
                for (int j = 0; j < 4; j++) {
#pragma unroll
                    for (int p = 0; p < 2; p++) {
                        int d = j * 8 + q2 + p;
                        float x0 = v[j][p], x1 = v[j + 4][p];
                        v[j][p]     = x0 * cr[d]      - x1 * sr[d];
                        v[j + 4][p] = x1 * cr[d + 32] + x0 * sr[d + 32];
                    }
                }
                if (mode == 0) {
#pragma unroll
                    for (int j = 0; j < 8; j++) { v[j][0] *= QSCALE; v[j][1] *= QSCALE; }
                }
            }
            __half* dp = dst + (((size_t)(bb * NHd + hh)) * Sn + s) * 64;
#pragma unroll
            for (int j = 0; j < 8; j++)
                *(uint32_t*)(dp + j * 8 + q2) = pack_h2(v[j][0], v[j][1]);
        }
    }
}

// ============================================================
// Standard HMMA GEMM (O-projection): fp32 out + bias
// ============================================================
__global__ __launch_bounds__(128, 2) void mm_hmma_kernel(
    const __half* __restrict__ Ah, const __half* __restrict__ Bh,
    const float* __restrict__ bias, float* __restrict__ Cm, int N, int K)
{
    extern __shared__ char sm[];
    const int t = threadIdx.x, wid = t >> 5, lane = t & 31;
    const int m0 = blockIdx.y * 128, n0 = blockIdx.x * 128;
    const uint32_t sbase = smem_u32(sm);

    const int warp_m = wid & 1;
    const int warp_n = wid >> 1;
    const int a_row = warp_m * 64 + (lane & 15);
    const int a_k8  = lane >> 4;
    const int b_row = warp_n * 64 + (lane & 7) + ((lane >> 4) << 3);
    const int b_k8  = (lane >> 3) & 1;

    float acc[4][8][4];
#pragma unroll
    for (int a = 0; a < 4; a++)
#pragma unroll
        for (int b = 0; b < 8; b++)
#pragma unroll
            for (int cq = 0; cq < 4; cq++) acc[a][b][cq] = 0.0f;

    GEMM_MAINLOOP(Ah + (size_t)m0 * K, Bh + (size_t)n0 * K, K);

    const int crow = m0 + warp_m * 64 + (lane >> 2);
    const int ccol = n0 + warp_n * 64 + (lane & 3) * 2;
#pragma unroll
    for (int j = 0; j < 8; j++) {
        int col = ccol + j * 8;
        float b0 = bias[col], b1 = bias[col + 1];
#pragma unroll
        for (int mt = 0; mt < 4; mt++) {
            int r0 = crow + mt * 16;
            float2 o0 = make_float2(acc[mt][j][0] + b0, acc[mt][j][1] + b1);
            float2 o1 = make_float2(acc[mt][j][2] + b0, acc[mt][j][3] + b1);
            *(float2*)(Cm + (size_t)r0 * N + col)       = o0;
            *(float2*)(Cm + (size_t)(r0 + 8) * N + col) = o1;
        }
    }
}

// ============================================================
// HMMA sliding-window attention (unchanged from R8)
// ============================================================
__global__ __launch_bounds__(256) void attn_mma_kernel(
    const __half* __restrict__ qh, const __half* __restrict__ kh,
    const __half* __restrict__ vh, __half* __restrict__ att)
{
    __shared__ __half Qs[2][64 * 64];
    __shared__ __half Ks[2][64 * 64];
    __shared__ __half Vs[2][64 * 64];

    const int t = threadIdx.x, wid = t >> 5, lane = t & 31;
    const int wm = wid & 3, hsel = wid >> 2;
    const int q0 = blockIdx.x * 64;
    const int hp = blockIdx.y;
    const int b  = blockIdx.z;
    const int h  = hp * 2 + hsel;
    const int hk = hp >> 1;

    const __half* Kg = kh + ((size_t)(b * HKVn + hk) * Sn) * 64;
    const __half* Vg = vh + ((size_t)(b * HKVn + hk) * Sn) * 64;

    const uint32_t sQ = smem_u32(Qs[hsel]);
    const uint32_t sK = smem_u32(Ks);
    const uint32_t sV = smem_u32(Vs);

    {
        const uint32_t sQ0 = smem_u32(Qs);
        for (int i = t; i < 1024; i += 256) {
            int hs = i >> 9, row = (i >> 3) & 63, c = i & 7;
            uint32_t sw = (uint32_t)hs * 8192u + (uint32_t)row * 128u +
                          (uint32_t)((c ^ (row & 7)) << 4);
            cp16(sQ0 + sw,
                 qh + (((size_t)(b * Hn + hp * 2 + hs) * Sn) + q0 + row) * 64 + c * 8);
        }
    }

    int lo = 0; while (q0 - 128 + lo * 64 < 0) lo++;
    int hi = 4; while (q0 - 128 + hi * 64 + 64 > Sn) hi--;

#define PREFETCH(it, buf) do { \
    int kb_ = q0 - 128 + (it) * 64; \
    const __half* Kt_ = Kg + (size_t)kb_ * 64; \
    const __half* Vt_ = Vg + (size_t)kb_ * 64; \
    uint32_t sk_ = sK + (uint32_t)(buf) * 8192u; \
    uint32_t sv_ = sV + (uint32_t)(buf) * 8192u; \
    for (int i_ = t; i_ < 512; i_ += 256) { \
        int row_ = i_ >> 3, c_ = i_ & 7; \
        uint32_t sw_ = (uint32_t)row_ * 128u + (uint32_t)((c_ ^ (row_ & 7)) << 4); \
        cp16(sk_ + sw_, Kt_ + row_ * 64 + c_ * 8); \
        cp16(sv_ + sw_, Vt_ + row_ * 64 + c_ * 8); \
    } } while (0)

    PREFETCH(lo, 0);
    CP_COMMIT();

    const int arow = wm * 16 + (lane & 15);
    const int ak8  = lane >> 4;
    const int brow = (lane & 7) + ((lane >> 4) << 3);
    const int bk8  = (lane >> 3) & 1;
    const int vrow = (lane & 7) + (((lane >> 3) & 1) << 3);
    const int vc8  = lane >> 4;

    const int r0g = q0 + wm * 16 + (lane >> 2);
    const int r1g = r0g + 8;

    float acc[8][4];
#pragma unroll
    for (int g = 0; g < 8; g++)
#pragma unroll
        for (int e = 0; e < 4; e++) acc[g][e] = 0.0f;
    float l0 = 0.0f, l1 = 0.0f;

    uint32_t qf[4][4];
    bool qloaded = false;

    for (int it = lo; it <= hi; ++it) {
        const int buf = (it - lo) & 1;
        if (it < hi) { PREFETCH(it + 1, buf ^ 1); CP_COMMIT(); CP_WAIT1(); }
        else { CP_WAIT0(); }
        __syncthreads();

        if (!qloaded) {
#pragma unroll
            for (int kblk = 0; kblk < 4; kblk++) {
                uint32_t ad = sQ + (uint32_t)arow * 128u +
                              (uint32_t)(((kblk * 2 + ak8) ^ (arow & 7)) << 4);
                ldmx4(qf[kblk], ad);
            }
            qloaded = true;
        }

        const int kb = q0 - 128 + it * 64;
        const uint32_t sk = sK + (uint32_t)buf * 8192u;
        const uint32_t sv = sV + (uint32_t)buf * 8192u;
        const bool need_mask = (it == 0) || (it == 4);

        float sc[8][4];
#pragma unroll
        for (int g = 0; g < 8; g++)
#pragma unroll
            for (int e = 0; e < 4; e++) sc[g][e] = 0.0f;
#pragma unroll
        for (int kblk = 0; kblk < 4; kblk++) {
#pragma unroll
            for (int g = 0; g < 4; g++) {
                int r = g * 16 + brow;
                uint32_t bd = sk + (uint32_t)r * 128u +
                              (uint32_t)(((kblk * 2 + bk8) ^ (r & 7)) << 4);
                uint32_t bf[4];
                ldmx4(bf, bd);
                mma16816(sc[2 * g],     qf[kblk], bf);
                mma16816(sc[2 * g + 1], qf[kblk], bf + 2);
            }
        }

        uint32_t pf[8][2];
        if (need_mask) {
#pragma unroll
            for (int g = 0; g < 8; g++) {
                int j0 = kb + g * 8 + (lane & 3) * 2;
                int j1 = j0 + 1;
                float p0 = (abs(j0 - r0g) <= 128) ? ex2f(sc[g][0]) : 0.0f;
                float p1 = (abs(j1 - r0g) <= 128) ? ex2f(sc[g][1]) : 0.0f;
                float p2 = (abs(j0 - r1g) <= 128) ? ex2f(sc[g][2]) : 0.0f;
                float p3 = (abs(j1 - r1g) <= 128) ? ex2f(sc[g][3]) : 0.0f;
                l0 += p0 + p1;
                l1 += p2 + p3;
                pf[g][0] = pack_h2(p0, p1);
                pf[g][1] = pack_h2(p2, p3);
            }
        } else {
#pragma unroll
            for (int g = 0; g < 8; g++) {
                float p0 = ex2f(sc[g][0]);
                float p1 = ex2f(sc[g][1]);
                float p2 = ex2f(sc[g][2]);
                float p3 = ex2f(sc[g][3]);
                l0 += p0 + p1;
                l1 += p2 + p3;
                pf[g][0] = pack_h2(p0, p1);
                pf[g][1] = pack_h2(p2, p3);
            }
        }

#pragma unroll
        for (int jj = 0; jj < 4; jj++) {
            uint32_t a[4] = { pf[2 * jj][0], pf[2 * jj][1],
                              pf[2 * jj + 1][0], pf[2 * jj + 1][1] };
#pragma unroll
            for (int dg = 0; dg < 4; dg++) {
                int r = jj * 16 + vrow;
                uint32_t bd = sv + (uint32_t)r * 128u +
                              (uint32_t)(((dg * 2 + vc8) ^ (r & 7)) << 4);
                uint32_t bf[4];
                ldmx4t(bf, bd);
                mma16816(acc[2 * dg],     a, bf);
                mma16816(acc[2 * dg + 1], a, bf + 2);
            }
        }
        __syncthreads();
    }
#undef PREFETCH

    l0 += __shfl_xor_sync(0xffffffffu, l0, 1);
    l0 += __shfl_xor_sync(0xffffffffu, l0, 2);
    l1 += __shfl_xor_sync(0xffffffffu, l1, 1);
    l1 += __shfl_xor_sync(0xffffffffu, l1, 2);
    const float i0 = 1.0f / l0, i1 = 1.0f / l1;
    const size_t base0 = ((size_t)(b * Sn) + r0g) * (Hn * DHn) + h * 64;
    const size_t base1 = ((size_t)(b * Sn) + r1g) * (Hn * DHn) + h * 64;
#pragma unroll
    for (int g = 0; g < 8; g++) {
        int d = g * 8 + (lane & 3) * 2;
        *(uint32_t*)(att + base0 + d) = pack_h2(acc[g][0] * i0, acc[g][1] * i0);
        *(uint32_t*)(att + base1 + d) = pack_h2(acc[g][2] * i1, acc[g][3] * i1);
    }
}

// ============================================================
extern "C" void kernel_launch(void* const* d_in, const int* in_sizes, int n_in,
                              void* d_out, int out_size)
{
    const float* x    = (const float*)d_in[0];
    const float* Wq   = (const float*)d_in[1];
    const float* bq   = (const float*)d_in[2];
    const float* Wk   = (const float*)d_in[3];
    const float* bk   = (const float*)d_in[4];
    const float* Wv   = (const float*)d_in[5];
    const float* bv   = (const float*)d_in[6];
    const float* Wo   = (const float*)d_in[7];
    const float* bo   = (const float*)d_in[8];
    const float* qn   = (const float*)d_in[9];
    const float* kn   = (const float*)d_in[10];
    const float* cosT = (const float*)d_in[11];
    const float* sinT = (const float*)d_in[12];
    float* out = (float*)d_out;

    __half *xh, *qh, *kh, *vh, *ah, *wqkv, *wo;
    cudaGetSymbolAddress((void**)&xh,   g_xh);
    cudaGetSymbolAddress((void**)&qh,   g_qh);
    cudaGetSymbolAddress((void**)&kh,   g_kh);
    cudaGetSymbolAddress((void**)&vh,   g_vh);
    cudaGetSymbolAddress((void**)&ah,   g_ah);
    cudaGetSymbolAddress((void**)&wqkv, g_wqkv);
    cudaGetSymbolAddress((void**)&wo,   g_wo);

    cudaFuncSetAttribute(mm_qkv_fused_kernel,
                         cudaFuncAttributeMaxDynamicSharedMemorySize, 65536);
    cudaFuncSetAttribute(mm_hmma_kernel,
                         cudaFuncAttributeMaxDynamicSharedMemorySize, 65536);
    const int DSMEM = 65536;

    prep_kernel<<<2560 + 16384, 256>>>(x, Wq, Wk, Wv, Wo, xh, wqkv, wo);

    mm_qkv_fused_kernel<<<dim3(12, 128), 128, DSMEM>>>(
        xh, wqkv, bq, bk, bv, qn, kn, cosT, sinT, qh, kh, vh);

    attn_mma_kernel<<<dim3(Sn / 64, Hn / 2, Bn), 256>>>(qh, kh, vh, ah);

    mm_hmma_kernel<<<dim3(8, 128), 128, DSMEM>>>(ah, wo, bo, out, 1024, 1024);
}